// round 1
// baseline (speedup 1.0000x reference)
#include <cuda_runtime.h>
#include <math.h>

#define NB 4
#define TT 2048
#define BT 8192      // NB*TT
#define CD 1024
#define FFD 4096
#define NH 16
#define DKD 64

// -------- scratch (device globals; no runtime allocation) --------
__device__ float g_qkv[BT * 3 * CD];   // 100.7 MB
__device__ float g_ctx[BT * CD];       // 33.5 MB
__device__ float g_tmp[BT * CD];       // 33.5 MB
__device__ float g_x1 [BT * CD];       // 33.5 MB
__device__ float g_h  [BT * FFD];      // 134.2 MB

// ============================================================
// Tiled fp32 GEMM: C[M,N] = A[M,K] @ B[K,N] + bias, optional ReLU
// BM=BN=128, BK=16, 256 threads, 8x8 per-thread tile.
// Assumes M%128==0, N%128==0, K%16==0 (true for all 4 calls).
// ============================================================
__global__ __launch_bounds__(256) void gemm128(
    const float* __restrict__ A, const float* __restrict__ B,
    const float* __restrict__ bias, float* __restrict__ C,
    int M, int N, int K, int relu)
{
    __shared__ float As[16][132];   // transposed A tile, padded
    __shared__ float Bs[16][128];

    const int tid = threadIdx.x;
    const int tx = tid & 15;        // 0..15  -> col group
    const int ty = tid >> 4;        // 0..15  -> row group
    const int bm0 = blockIdx.y * 128;
    const int bn0 = blockIdx.x * 128;

    float acc[8][8];
#pragma unroll
    for (int i = 0; i < 8; i++)
#pragma unroll
        for (int j = 0; j < 8; j++) acc[i][j] = 0.f;

    for (int k0 = 0; k0 < K; k0 += 16) {
        // load A tile [128 x 16], store transposed
#pragma unroll
        for (int s = 0; s < 2; s++) {
            int i = tid + 256 * s;          // 0..511 float4s
            int ar = i >> 2, ac = i & 3;
            float4 v = *(const float4*)(A + (size_t)(bm0 + ar) * K + k0 + ac * 4);
            As[ac * 4 + 0][ar] = v.x;
            As[ac * 4 + 1][ar] = v.y;
            As[ac * 4 + 2][ar] = v.z;
            As[ac * 4 + 3][ar] = v.w;
        }
        // load B tile [16 x 128]
#pragma unroll
        for (int s = 0; s < 2; s++) {
            int i = tid + 256 * s;
            int br = i >> 5, bc = i & 31;
            *(float4*)&Bs[br][bc * 4] =
                *(const float4*)(B + (size_t)(k0 + br) * N + bn0 + bc * 4);
        }
        __syncthreads();

#pragma unroll
        for (int kk = 0; kk < 16; kk++) {
            float a[8], b[8];
            *(float4*)&a[0] = *(const float4*)&As[kk][ty * 8];
            *(float4*)&a[4] = *(const float4*)&As[kk][ty * 8 + 4];
            *(float4*)&b[0] = *(const float4*)&Bs[kk][tx * 8];
            *(float4*)&b[4] = *(const float4*)&Bs[kk][tx * 8 + 4];
#pragma unroll
            for (int i = 0; i < 8; i++)
#pragma unroll
                for (int j = 0; j < 8; j++)
                    acc[i][j] += a[i] * b[j];
        }
        __syncthreads();
    }

    float bv[8];
    *(float4*)&bv[0] = *(const float4*)(bias + bn0 + tx * 8);
    *(float4*)&bv[4] = *(const float4*)(bias + bn0 + tx * 8 + 4);

#pragma unroll
    for (int i = 0; i < 8; i++) {
        float* cp = C + (size_t)(bm0 + ty * 8 + i) * N + bn0 + tx * 8;
        float v[8];
#pragma unroll
        for (int j = 0; j < 8; j++) {
            float t = acc[i][j] + bv[j];
            v[j] = relu ? fmaxf(t, 0.f) : t;
        }
        *(float4*)cp = *(float4*)&v[0];
        *(float4*)(cp + 4) = *(float4*)&v[4];
    }
}

// ============================================================
// Flash-attention (fp32 SIMT). Block = 64 queries of one (b,h).
// Grid: (T/64, B*H). 256 threads. smem tiles 64x64 with XOR swizzle.
// qkv layout per row (3C): [q(1024) | k(1024) | v(1024)], head h at h*64.
// Output ctx: [BT, C] with col = h*64 + d.
// ============================================================
__device__ __forceinline__ int sw_idx(int row, int c4) {
    // chunk(16B)-granular XOR swizzle; row in 0..63, c4 in 0..15
    return row * 64 + ((c4 ^ ((row & 7) ^ (row >> 3))) << 2);
}

__global__ __launch_bounds__(256) void attn_kernel(
    const float* __restrict__ qkv, float* __restrict__ ctx)
{
    __shared__ float Qsm[64 * 64];
    __shared__ float Ksm[64 * 64];
    __shared__ float Vsm[64 * 64];

    const int tid = threadIdx.x;
    const int bh = blockIdx.y;
    const int b = bh >> 4, h = bh & 15;
    const int t0 = blockIdx.x * 64;
    const float* base = qkv + (size_t)b * TT * (3 * CD) + h * DKD;

    // load + pre-scale Q tile (1/sqrt(64) = 0.125)
#pragma unroll
    for (int s = 0; s < 4; s++) {
        int i4 = tid + 256 * s;
        int qr = i4 >> 4, d4 = i4 & 15;
        float4 v = *(const float4*)(base + (size_t)(t0 + qr) * (3 * CD) + d4 * 4);
        v.x *= 0.125f; v.y *= 0.125f; v.z *= 0.125f; v.w *= 0.125f;
        *(float4*)&Qsm[sw_idx(qr, d4)] = v;
    }

    const int r = tid >> 2;        // query row 0..63
    const int g = tid & 3;         // group: owns keys [g*16,g*16+16) and dims [g*16,g*16+16)
    const int kc = g * 16;

    float m = -INFINITY, l = 0.f;
    float o[16];
#pragma unroll
    for (int i = 0; i < 16; i++) o[i] = 0.f;

    for (int kt = 0; kt < TT / 64; kt++) {
        __syncthreads();
        const int k0 = kt * 64;
#pragma unroll
        for (int s = 0; s < 4; s++) {
            int i4 = tid + 256 * s;
            int kr = i4 >> 4, d4 = i4 & 15;
            const float* rp = base + (size_t)(k0 + kr) * (3 * CD);
            *(float4*)&Ksm[sw_idx(kr, d4)] = *(const float4*)(rp + CD + d4 * 4);
            *(float4*)&Vsm[sw_idx(kr, d4)] = *(const float4*)(rp + 2 * CD + d4 * 4);
        }
        __syncthreads();

        // scores: sc[j] = q[r] . k[kc+j]
        float sc[16];
#pragma unroll
        for (int j = 0; j < 16; j++) sc[j] = 0.f;
#pragma unroll
        for (int db = 0; db < 4; db++) {
            float qf[16];
#pragma unroll
            for (int u = 0; u < 4; u++) {
                float4 qv = *(const float4*)&Qsm[sw_idx(r, db * 4 + u)];
                qf[u * 4 + 0] = qv.x; qf[u * 4 + 1] = qv.y;
                qf[u * 4 + 2] = qv.z; qf[u * 4 + 3] = qv.w;
            }
#pragma unroll
            for (int j = 0; j < 16; j++) {
                float acc = sc[j];
#pragma unroll
                for (int u = 0; u < 4; u++) {
                    float4 kv = *(const float4*)&Ksm[sw_idx(kc + j, db * 4 + u)];
                    acc += qf[u * 4 + 0] * kv.x + qf[u * 4 + 1] * kv.y
                         + qf[u * 4 + 2] * kv.z + qf[u * 4 + 3] * kv.w;
                }
                sc[j] = acc;
            }
        }

        // online softmax (row state shared by the 4-lane group via width-4 shuffles)
        float mt = sc[0];
#pragma unroll
        for (int j = 1; j < 16; j++) mt = fmaxf(mt, sc[j]);
        mt = fmaxf(mt, __shfl_xor_sync(0xffffffffu, mt, 1, 4));
        mt = fmaxf(mt, __shfl_xor_sync(0xffffffffu, mt, 2, 4));
        float mn = fmaxf(m, mt);
        float alpha = __expf(m - mn);
        float ls = 0.f;
#pragma unroll
        for (int j = 0; j < 16; j++) { sc[j] = __expf(sc[j] - mn); ls += sc[j]; }
        ls += __shfl_xor_sync(0xffffffffu, ls, 1, 4);
        ls += __shfl_xor_sync(0xffffffffu, ls, 2, 4);
        l = l * alpha + ls;
        m = mn;
#pragma unroll
        for (int i = 0; i < 16; i++) o[i] *= alpha;

        // O += P @ V  (gather sibling p via width-4 shuffle)
#pragma unroll
        for (int g2 = 0; g2 < 4; g2++) {
#pragma unroll
            for (int j = 0; j < 16; j++) {
                float pj = __shfl_sync(0xffffffffu, sc[j], g2, 4);
                int key = g2 * 16 + j;
#pragma unroll
                for (int u = 0; u < 4; u++) {
                    float4 vv = *(const float4*)&Vsm[sw_idx(key, g * 4 + u)];
                    o[u * 4 + 0] += pj * vv.x; o[u * 4 + 1] += pj * vv.y;
                    o[u * 4 + 2] += pj * vv.z; o[u * 4 + 3] += pj * vv.w;
                }
            }
        }
    }

    float inv = 1.f / l;
    float* op = ctx + (size_t)(b * TT + t0 + r) * CD + h * DKD + g * 16;
#pragma unroll
    for (int u = 0; u < 4; u++) {
        float4 w;
        w.x = o[u * 4 + 0] * inv; w.y = o[u * 4 + 1] * inv;
        w.z = o[u * 4 + 2] * inv; w.w = o[u * 4 + 3] * inv;
        *(float4*)(op + u * 4) = w;
    }
}

// ============================================================
// out = LayerNorm(x + res) * g + b ; one block per row, 256 threads, C=1024
// ============================================================
__global__ __launch_bounds__(256) void add_ln_kernel(
    const float* __restrict__ x, const float* __restrict__ res,
    const float* __restrict__ gg, const float* __restrict__ bb,
    float* __restrict__ out)
{
    const int row = blockIdx.x, tid = threadIdx.x;
    float4 xv = ((const float4*)(x + (size_t)row * CD))[tid];
    float4 rv = ((const float4*)(res + (size_t)row * CD))[tid];
    float y0 = xv.x + rv.x, y1 = xv.y + rv.y, y2 = xv.z + rv.z, y3 = xv.w + rv.w;
    float s = y0 + y1 + y2 + y3;
    float ss = y0 * y0 + y1 * y1 + y2 * y2 + y3 * y3;
#pragma unroll
    for (int off = 16; off; off >>= 1) {
        s  += __shfl_xor_sync(0xffffffffu, s, off);
        ss += __shfl_xor_sync(0xffffffffu, ss, off);
    }
    __shared__ float rs[8], rss[8];
    if ((tid & 31) == 0) { rs[tid >> 5] = s; rss[tid >> 5] = ss; }
    __syncthreads();
    float tot = 0.f, tots = 0.f;
#pragma unroll
    for (int i = 0; i < 8; i++) { tot += rs[i]; tots += rss[i]; }
    float mean = tot * (1.f / CD);
    float var = tots * (1.f / CD) - mean * mean;
    float iv = rsqrtf(var + 1e-5f);
    float4 gv = ((const float4*)gg)[tid];
    float4 bv = ((const float4*)bb)[tid];
    float4 ov;
    ov.x = (y0 - mean) * iv * gv.x + bv.x;
    ov.y = (y1 - mean) * iv * gv.y + bv.y;
    ov.z = (y2 - mean) * iv * gv.z + bv.z;
    ov.w = (y3 - mean) * iv * gv.w + bv.w;
    ((float4*)(out + (size_t)row * CD))[tid] = ov;
}

// ============================================================
extern "C" void kernel_launch(void* const* d_in, const int* in_sizes, int n_in,
                              void* d_out, int out_size)
{
    const float* x     = (const float*)d_in[0];
    const float* w_qkv = (const float*)d_in[1];
    const float* b_qkv = (const float*)d_in[2];
    const float* w_out = (const float*)d_in[3];
    const float* b_out = (const float*)d_in[4];
    const float* w1    = (const float*)d_in[5];
    const float* b1    = (const float*)d_in[6];
    const float* w2    = (const float*)d_in[7];
    const float* b2    = (const float*)d_in[8];
    const float* ln1g  = (const float*)d_in[9];
    const float* ln1b  = (const float*)d_in[10];
    const float* ln2g  = (const float*)d_in[11];
    const float* ln2b  = (const float*)d_in[12];
    float* out = (float*)d_out;

    float *qkv, *ctx, *tmp, *x1, *hbuf;
    cudaGetSymbolAddress((void**)&qkv,  g_qkv);
    cudaGetSymbolAddress((void**)&ctx,  g_ctx);
    cudaGetSymbolAddress((void**)&tmp,  g_tmp);
    cudaGetSymbolAddress((void**)&x1,   g_x1);
    cudaGetSymbolAddress((void**)&hbuf, g_h);

    dim3 blk(256);

    // 1) qkv = x @ w_qkv + b_qkv            [8192, 3072]
    gemm128<<<dim3(3 * CD / 128, BT / 128), blk>>>(x, w_qkv, b_qkv, qkv, BT, 3 * CD, CD, 0);
    // 2) ctx = attention(q,k,v)             [8192, 1024]
    attn_kernel<<<dim3(TT / 64, NB * NH), blk>>>(qkv, ctx);
    // 3) tmp = ctx @ w_out + b_out
    gemm128<<<dim3(CD / 128, BT / 128), blk>>>(ctx, w_out, b_out, tmp, BT, CD, CD, 0);
    // 4) x1 = LN(x + tmp)
    add_ln_kernel<<<BT, 256>>>(x, tmp, ln1g, ln1b, x1);
    // 5) h = relu(x1 @ w1 + b1)             [8192, 4096]
    gemm128<<<dim3(FFD / 128, BT / 128), blk>>>(x1, w1, b1, hbuf, BT, FFD, CD, 1);
    // 6) tmp = h @ w2 + b2
    gemm128<<<dim3(CD / 128, BT / 128), blk>>>(hbuf, w2, b2, tmp, BT, CD, FFD, 0);
    // 7) out = LN(x1 + tmp)
    add_ln_kernel<<<BT, 256>>>(x1, tmp, ln2g, ln2b, out);
}

// round 4
// speedup vs baseline: 1.3435x; 1.3435x over previous
#include <cuda_runtime.h>
#include <cuda_bf16.h>
#include <math.h>
#include <stdint.h>

#define NB 4
#define TT 2048
#define BT 8192      // NB*TT
#define CD 1024
#define FFD 4096
#define NH 16
#define DKD 64

// ---------------- scratch (device globals) ----------------
__device__ float g_qkv[BT * 3 * CD];                 // fp32
__device__ float g_tmp[BT * CD];
__device__ float g_x1 [BT * CD];
__device__ __nv_bfloat16 g_a1hi[BT * CD];            // activations (x / ctx / x1)
__device__ __nv_bfloat16 g_a1lo[BT * CD];
__device__ __nv_bfloat16 g_hhi [BT * FFD];           // FFN hidden
__device__ __nv_bfloat16 g_hlo [BT * FFD];
__device__ __nv_bfloat16 g_wthi[FFD * CD];           // transposed weights [N,K]
__device__ __nv_bfloat16 g_wtlo[FFD * CD];

// ============================================================
// mma.sync bf16x3 GEMM: C[M,N] = A[M,K] @ B^T  (B stored [N,K])
// 128x128 tile, BK=32, 8 warps x (64x32), cp.async double buffer.
// ============================================================
#define BKC 32
#define AST 40                      // smem row stride (bf16 elems), 80B -> conflict-free ldmatrix
#define OF_AH 0
#define OF_AL (128 * AST)
#define OF_BH (2 * 128 * AST)
#define OF_BL (3 * 128 * AST)
#define BUF_ELEMS (4 * 128 * AST)   // 20480 elems
#define BUF_BYTES (BUF_ELEMS * 2)   // 40960 B
#define GSM_BYTES (2 * BUF_BYTES)   // 81920 B

__device__ __forceinline__ uint32_t smem_to_u32(const void* p) {
    uint32_t a;
    asm("{ .reg .u64 t; cvta.to.shared.u64 t, %1; cvt.u32.u64 %0, t; }" : "=r"(a) : "l"(p));
    return a;
}
#define CP_ASYNC16(sm, gp) \
    asm volatile("cp.async.cg.shared.global [%0], [%1], 16;" :: "r"(sm), "l"(gp))
#define CP_COMMIT() asm volatile("cp.async.commit_group;" ::: "memory")
#define CP_WAIT0()  asm volatile("cp.async.wait_group 0;" ::: "memory")
#define CP_WAIT1()  asm volatile("cp.async.wait_group 1;" ::: "memory")

__device__ __forceinline__ void ldm_x4(uint32_t* r, uint32_t addr) {
    asm volatile("ldmatrix.sync.aligned.m8n8.x4.shared.b16 {%0,%1,%2,%3}, [%4];"
        : "=r"(r[0]), "=r"(r[1]), "=r"(r[2]), "=r"(r[3]) : "r"(addr));
}
__device__ __forceinline__ void mma_bf16(float* c, const uint32_t* a, const uint32_t* b) {
    asm volatile("mma.sync.aligned.m16n8k16.row.col.f32.bf16.bf16.f32 "
        "{%0,%1,%2,%3}, {%4,%5,%6,%7}, {%8,%9}, {%0,%1,%2,%3};"
        : "+f"(c[0]), "+f"(c[1]), "+f"(c[2]), "+f"(c[3])
        : "r"(a[0]), "r"(a[1]), "r"(a[2]), "r"(a[3]), "r"(b[0]), "r"(b[1]));
}

__device__ __forceinline__ void load_chunk(uint32_t sbuf,
    const __nv_bfloat16* Ah, const __nv_bfloat16* Al,
    const __nv_bfloat16* Bh, const __nv_bfloat16* Bl,
    int K, int k0, int tid)
{
#pragma unroll
    for (int j = 0; j < 2; j++) {
        int v = tid + 256 * j;
        int row = v >> 2, c4 = v & 3;
        uint32_t doff = (uint32_t)(row * AST + c4 * 8) * 2;
        size_t goff = (size_t)row * K + k0 + c4 * 8;
        CP_ASYNC16(sbuf + OF_AH * 2 + doff, Ah + goff);
        CP_ASYNC16(sbuf + OF_AL * 2 + doff, Al + goff);
        CP_ASYNC16(sbuf + OF_BH * 2 + doff, Bh + goff);
        CP_ASYNC16(sbuf + OF_BL * 2 + doff, Bl + goff);
    }
}

__global__ __launch_bounds__(256)
void gemm_mma(const __nv_bfloat16* __restrict__ Ahi, const __nv_bfloat16* __restrict__ Alo,
              const __nv_bfloat16* __restrict__ Bhi, const __nv_bfloat16* __restrict__ Blo,
              const float* __restrict__ bias,
              float* __restrict__ Cf, __nv_bfloat16* __restrict__ Chi, __nv_bfloat16* __restrict__ Clo,
              int N, int K, int relu)
{
    extern __shared__ char dsm[];
    const uint32_t sb = smem_to_u32(dsm);
    const int tid = threadIdx.x;
    const int lane = tid & 31;
    const int w = tid >> 5;
    const int wm = w & 1, wn = w >> 1;
    const int bm0 = blockIdx.y * 128;
    const int bn0 = blockIdx.x * 128;

    const __nv_bfloat16* Ah = Ahi + (size_t)bm0 * K;
    const __nv_bfloat16* Al = Alo + (size_t)bm0 * K;
    const __nv_bfloat16* Bh = Bhi + (size_t)bn0 * K;
    const __nv_bfloat16* Bl = Blo + (size_t)bn0 * K;

    float acc[4][4][4];
#pragma unroll
    for (int a = 0; a < 4; a++)
#pragma unroll
        for (int b = 0; b < 4; b++)
#pragma unroll
            for (int c = 0; c < 4; c++) acc[a][b][c] = 0.f;

    // ldmatrix lane address components
    const int arow = (lane & 7) + ((lane >> 3) & 1) * 8;
    const int acol = ((lane >> 4) & 1) * 8;
    const int brow = (lane & 7) + ((lane >> 4) & 1) * 8;
    const int bcol = ((lane >> 3) & 1) * 8;

    const int nch = K / BKC;
    load_chunk(sb, Ah, Al, Bh, Bl, K, 0, tid);
    CP_COMMIT();

    for (int i = 0; i < nch; i++) {
        if (i + 1 < nch) {
            load_chunk(sb + ((i + 1) & 1) * BUF_BYTES, Ah, Al, Bh, Bl, K, (i + 1) * BKC, tid);
            CP_COMMIT();
            CP_WAIT1();
        } else {
            CP_WAIT0();
        }
        __syncthreads();

        const uint32_t buf = sb + (i & 1) * BUF_BYTES;
#pragma unroll
        for (int kk = 0; kk < 2; kk++) {
            const int kb = kk * 16;
            uint32_t ah[4][4], al[4][4], bh[2][4], bl[2][4];
#pragma unroll
            for (int mt = 0; mt < 4; mt++) {
                int r = wm * 64 + mt * 16 + arow;
                uint32_t off = (uint32_t)(r * AST + kb + acol) * 2;
                ldm_x4(ah[mt], buf + OF_AH * 2 + off);
                ldm_x4(al[mt], buf + OF_AL * 2 + off);
            }
#pragma unroll
            for (int nt2 = 0; nt2 < 2; nt2++) {
                int r = wn * 32 + nt2 * 16 + brow;
                uint32_t off = (uint32_t)(r * AST + kb + bcol) * 2;
                ldm_x4(bh[nt2], buf + OF_BH * 2 + off);
                ldm_x4(bl[nt2], buf + OF_BL * 2 + off);
            }
#pragma unroll
            for (int mt = 0; mt < 4; mt++)
#pragma unroll
                for (int nt = 0; nt < 4; nt++) {
                    const uint32_t* fh = &bh[nt >> 1][(nt & 1) * 2];
                    const uint32_t* fl = &bl[nt >> 1][(nt & 1) * 2];
                    mma_bf16(acc[mt][nt], ah[mt], fh);
                    mma_bf16(acc[mt][nt], ah[mt], fl);
                    mma_bf16(acc[mt][nt], al[mt], fh);
                }
        }
        __syncthreads();
    }

    // epilogue
    const int tr = lane >> 2, tc = (lane & 3) * 2;
    const int r0 = bm0 + wm * 64;
    const int c0 = bn0 + wn * 32;
#pragma unroll
    for (int mt = 0; mt < 4; mt++) {
#pragma unroll
        for (int nt = 0; nt < 4; nt++) {
            const int col = c0 + nt * 8 + tc;
            const float2 bv = *(const float2*)(bias + col);
#pragma unroll
            for (int h = 0; h < 2; h++) {
                const int row = r0 + mt * 16 + tr + h * 8;
                float v0 = acc[mt][nt][h * 2 + 0] + bv.x;
                float v1 = acc[mt][nt][h * 2 + 1] + bv.y;
                if (relu) { v0 = fmaxf(v0, 0.f); v1 = fmaxf(v1, 0.f); }
                if (Cf) {
                    float2 o = {v0, v1};
                    *(float2*)(Cf + (size_t)row * N + col) = o;
                }
                if (Chi) {
                    __nv_bfloat16 h0 = __float2bfloat16_rn(v0);
                    __nv_bfloat16 h1 = __float2bfloat16_rn(v1);
                    __nv_bfloat162 hp = __halves2bfloat162(h0, h1);
                    __nv_bfloat162 lp = __halves2bfloat162(
                        __float2bfloat16_rn(v0 - __bfloat162float(h0)),
                        __float2bfloat16_rn(v1 - __bfloat162float(h1)));
                    *(__nv_bfloat162*)(Chi + (size_t)row * N + col) = hp;
                    *(__nv_bfloat162*)(Clo + (size_t)row * N + col) = lp;
                }
            }
        }
    }
}

// ============================================================
// conversions
// ============================================================
__global__ __launch_bounds__(256) void convert_act(const float* __restrict__ in,
    __nv_bfloat16* __restrict__ ohi, __nv_bfloat16* __restrict__ olo, int n4)
{
    int i = blockIdx.x * 256 + threadIdx.x;
    if (i >= n4) return;
    float4 v = ((const float4*)in)[i];
    float vv[4] = {v.x, v.y, v.z, v.w};
    __nv_bfloat162 h[2], l[2];
#pragma unroll
    for (int u = 0; u < 2; u++) {
        __nv_bfloat16 h0 = __float2bfloat16_rn(vv[2 * u]);
        __nv_bfloat16 h1 = __float2bfloat16_rn(vv[2 * u + 1]);
        h[u] = __halves2bfloat162(h0, h1);
        l[u] = __halves2bfloat162(__float2bfloat16_rn(vv[2 * u] - __bfloat162float(h0)),
                                  __float2bfloat16_rn(vv[2 * u + 1] - __bfloat162float(h1)));
    }
    ((uint2*)ohi)[i] = *(uint2*)h;
    ((uint2*)olo)[i] = *(uint2*)l;
}

// weight [K,N] fp32 -> [N,K] bf16 hi/lo (transpose + split)
__global__ void convert_wT(const float* __restrict__ in,
    __nv_bfloat16* __restrict__ ohi, __nv_bfloat16* __restrict__ olo, int K, int N)
{
    __shared__ float t[32][33];
    int n0 = blockIdx.x * 32, k0 = blockIdx.y * 32;
    int tx = threadIdx.x, ty = threadIdx.y;
    for (int j = ty; j < 32; j += 8) t[j][tx] = in[(size_t)(k0 + j) * N + n0 + tx];
    __syncthreads();
    for (int j = ty; j < 32; j += 8) {
        float v = t[tx][j];
        __nv_bfloat16 h = __float2bfloat16_rn(v);
        size_t o = (size_t)(n0 + j) * K + k0 + tx;
        ohi[o] = h;
        olo[o] = __float2bfloat16_rn(v - __bfloat162float(h));
    }
}

// ============================================================
// Flash-attention (fp32 SIMT), epilogue emits bf16 hi/lo ctx
// ============================================================
__device__ __forceinline__ int sw_idx(int row, int c4) {
    return row * 64 + ((c4 ^ ((row & 7) ^ (row >> 3))) << 2);
}

__global__ __launch_bounds__(256) void attn_kernel(
    const float* __restrict__ qkv,
    __nv_bfloat16* __restrict__ chi, __nv_bfloat16* __restrict__ clo)
{
    __shared__ float Qsm[64 * 64];
    __shared__ float Ksm[64 * 64];
    __shared__ float Vsm[64 * 64];

    const int tid = threadIdx.x;
    const int bh = blockIdx.y;
    const int b = bh >> 4, h = bh & 15;
    const int t0 = blockIdx.x * 64;
    const float* base = qkv + (size_t)b * TT * (3 * CD) + h * DKD;

#pragma unroll
    for (int s = 0; s < 4; s++) {
        int i4 = tid + 256 * s;
        int qr = i4 >> 4, d4 = i4 & 15;
        float4 v = *(const float4*)(base + (size_t)(t0 + qr) * (3 * CD) + d4 * 4);
        v.x *= 0.125f; v.y *= 0.125f; v.z *= 0.125f; v.w *= 0.125f;
        *(float4*)&Qsm[sw_idx(qr, d4)] = v;
    }

    const int r = tid >> 2;
    const int g = tid & 3;
    const int kc = g * 16;

    float m = -INFINITY, l = 0.f;
    float o[16];
#pragma unroll
    for (int i = 0; i < 16; i++) o[i] = 0.f;

    for (int kt = 0; kt < TT / 64; kt++) {
        __syncthreads();
        const int k0 = kt * 64;
#pragma unroll
        for (int s = 0; s < 4; s++) {
            int i4 = tid + 256 * s;
            int kr = i4 >> 4, d4 = i4 & 15;
            const float* rp = base + (size_t)(k0 + kr) * (3 * CD);
            *(float4*)&Ksm[sw_idx(kr, d4)] = *(const float4*)(rp + CD + d4 * 4);
            *(float4*)&Vsm[sw_idx(kr, d4)] = *(const float4*)(rp + 2 * CD + d4 * 4);
        }
        __syncthreads();

        float sc[16];
#pragma unroll
        for (int j = 0; j < 16; j++) sc[j] = 0.f;
#pragma unroll
        for (int db = 0; db < 4; db++) {
            float qf[16];
#pragma unroll
            for (int u = 0; u < 4; u++) {
                float4 qv = *(const float4*)&Qsm[sw_idx(r, db * 4 + u)];
                qf[u * 4 + 0] = qv.x; qf[u * 4 + 1] = qv.y;
                qf[u * 4 + 2] = qv.z; qf[u * 4 + 3] = qv.w;
            }
#pragma unroll
            for (int j = 0; j < 16; j++) {
                float acc = sc[j];
#pragma unroll
                for (int u = 0; u < 4; u++) {
                    float4 kv = *(const float4*)&Ksm[sw_idx(kc + j, db * 4 + u)];
                    acc += qf[u * 4 + 0] * kv.x + qf[u * 4 + 1] * kv.y
                         + qf[u * 4 + 2] * kv.z + qf[u * 4 + 3] * kv.w;
                }
                sc[j] = acc;
            }
        }

        float mt = sc[0];
#pragma unroll
        for (int j = 1; j < 16; j++) mt = fmaxf(mt, sc[j]);
        mt = fmaxf(mt, __shfl_xor_sync(0xffffffffu, mt, 1, 4));
        mt = fmaxf(mt, __shfl_xor_sync(0xffffffffu, mt, 2, 4));
        float mn = fmaxf(m, mt);
        float alpha = __expf(m - mn);
        float ls = 0.f;
#pragma unroll
        for (int j = 0; j < 16; j++) { sc[j] = __expf(sc[j] - mn); ls += sc[j]; }
        ls += __shfl_xor_sync(0xffffffffu, ls, 1, 4);
        ls += __shfl_xor_sync(0xffffffffu, ls, 2, 4);
        l = l * alpha + ls;
        m = mn;
#pragma unroll
        for (int i = 0; i < 16; i++) o[i] *= alpha;

#pragma unroll
        for (int g2 = 0; g2 < 4; g2++) {
#pragma unroll
            for (int j = 0; j < 16; j++) {
                float pj = __shfl_sync(0xffffffffu, sc[j], g2, 4);
                int key = g2 * 16 + j;
#pragma unroll
                for (int u = 0; u < 4; u++) {
                    float4 vv = *(const float4*)&Vsm[sw_idx(key, g * 4 + u)];
                    o[u * 4 + 0] += pj * vv.x; o[u * 4 + 1] += pj * vv.y;
                    o[u * 4 + 2] += pj * vv.z; o[u * 4 + 3] += pj * vv.w;
                }
            }
        }
    }

    float inv = 1.f / l;
    size_t off = (size_t)(b * TT + t0 + r) * CD + h * DKD + g * 16;
#pragma unroll
    for (int u = 0; u < 4; u++) {
        float w0 = o[u * 4 + 0] * inv, w1 = o[u * 4 + 1] * inv;
        float w2 = o[u * 4 + 2] * inv, w3 = o[u * 4 + 3] * inv;
        __nv_bfloat16 h0 = __float2bfloat16_rn(w0), h1 = __float2bfloat16_rn(w1);
        __nv_bfloat16 h2 = __float2bfloat16_rn(w2), h3 = __float2bfloat16_rn(w3);
        __nv_bfloat162 hp[2] = {__halves2bfloat162(h0, h1), __halves2bfloat162(h2, h3)};
        __nv_bfloat162 lp[2] = {
            __halves2bfloat162(__float2bfloat16_rn(w0 - __bfloat162float(h0)),
                               __float2bfloat16_rn(w1 - __bfloat162float(h1))),
            __halves2bfloat162(__float2bfloat16_rn(w2 - __bfloat162float(h2)),
                               __float2bfloat16_rn(w3 - __bfloat162float(h3)))};
        *(uint2*)(chi + off + u * 4) = *(uint2*)hp;
        *(uint2*)(clo + off + u * 4) = *(uint2*)lp;
    }
}

// ============================================================
// out = LayerNorm(x + res); optional bf16 hi/lo emission
// ============================================================
__global__ __launch_bounds__(256) void add_ln_kernel(
    const float* __restrict__ x, const float* __restrict__ res,
    const float* __restrict__ gg, const float* __restrict__ bb,
    float* __restrict__ out, __nv_bfloat16* __restrict__ ohi, __nv_bfloat16* __restrict__ olo)
{
    const int row = blockIdx.x, tid = threadIdx.x;
    float4 xv = ((const float4*)(x + (size_t)row * CD))[tid];
    float4 rv = ((const float4*)(res + (size_t)row * CD))[tid];
    float y0 = xv.x + rv.x, y1 = xv.y + rv.y, y2 = xv.z + rv.z, y3 = xv.w + rv.w;
    float s = y0 + y1 + y2 + y3;
    float ss = y0 * y0 + y1 * y1 + y2 * y2 + y3 * y3;
#pragma unroll
    for (int off = 16; off; off >>= 1) {
        s  += __shfl_xor_sync(0xffffffffu, s, off);
        ss += __shfl_xor_sync(0xffffffffu, ss, off);
    }
    __shared__ float rs[8], rss[8];
    if ((tid & 31) == 0) { rs[tid >> 5] = s; rss[tid >> 5] = ss; }
    __syncthreads();
    float tot = 0.f, tots = 0.f;
#pragma unroll
    for (int i = 0; i < 8; i++) { tot += rs[i]; tots += rss[i]; }
    float mean = tot * (1.f / CD);
    float var = tots * (1.f / CD) - mean * mean;
    float iv = rsqrtf(var + 1e-5f);
    float4 gv = ((const float4*)gg)[tid];
    float4 bv = ((const float4*)bb)[tid];
    float w[4];
    w[0] = (y0 - mean) * iv * gv.x + bv.x;
    w[1] = (y1 - mean) * iv * gv.y + bv.y;
    w[2] = (y2 - mean) * iv * gv.z + bv.z;
    w[3] = (y3 - mean) * iv * gv.w + bv.w;
    float4 ov = {w[0], w[1], w[2], w[3]};
    ((float4*)(out + (size_t)row * CD))[tid] = ov;
    if (ohi) {
        __nv_bfloat16 h0 = __float2bfloat16_rn(w[0]), h1 = __float2bfloat16_rn(w[1]);
        __nv_bfloat16 h2 = __float2bfloat16_rn(w[2]), h3 = __float2bfloat16_rn(w[3]);
        __nv_bfloat162 hp[2] = {__halves2bfloat162(h0, h1), __halves2bfloat162(h2, h3)};
        __nv_bfloat162 lp[2] = {
            __halves2bfloat162(__float2bfloat16_rn(w[0] - __bfloat162float(h0)),
                               __float2bfloat16_rn(w[1] - __bfloat162float(h1))),
            __halves2bfloat162(__float2bfloat16_rn(w[2] - __bfloat162float(h2)),
                               __float2bfloat16_rn(w[3] - __bfloat162float(h3)))};
        size_t off = (size_t)row * CD + tid * 4;
        *(uint2*)(ohi + off) = *(uint2*)hp;
        *(uint2*)(olo + off) = *(uint2*)lp;
    }
}

// ============================================================
extern "C" void kernel_launch(void* const* d_in, const int* in_sizes, int n_in,
                              void* d_out, int out_size)
{
    const float* x     = (const float*)d_in[0];
    const float* w_qkv = (const float*)d_in[1];
    const float* b_qkv = (const float*)d_in[2];
    const float* w_out = (const float*)d_in[3];
    const float* b_out = (const float*)d_in[4];
    const float* w1    = (const float*)d_in[5];
    const float* b1    = (const float*)d_in[6];
    const float* w2    = (const float*)d_in[7];
    const float* b2    = (const float*)d_in[8];
    const float* ln1g  = (const float*)d_in[9];
    const float* ln1b  = (const float*)d_in[10];
    const float* ln2g  = (const float*)d_in[11];
    const float* ln2b  = (const float*)d_in[12];
    float* out = (float*)d_out;

    float *qkv, *tmp, *x1;
    __nv_bfloat16 *a1h, *a1l, *hh, *hl, *wth, *wtl;
    cudaGetSymbolAddress((void**)&qkv, g_qkv);
    cudaGetSymbolAddress((void**)&tmp, g_tmp);
    cudaGetSymbolAddress((void**)&x1,  g_x1);
    cudaGetSymbolAddress((void**)&a1h, g_a1hi);
    cudaGetSymbolAddress((void**)&a1l, g_a1lo);
    cudaGetSymbolAddress((void**)&hh,  g_hhi);
    cudaGetSymbolAddress((void**)&hl,  g_hlo);
    cudaGetSymbolAddress((void**)&wth, g_wthi);
    cudaGetSymbolAddress((void**)&wtl, g_wtlo);

    cudaFuncSetAttribute(gemm_mma, cudaFuncAttributeMaxDynamicSharedMemorySize, GSM_BYTES);

    dim3 tblk(32, 8);

    // x -> bf16 hi/lo
    convert_act<<<(BT * CD / 4 + 255) / 256, 256>>>(x, a1h, a1l, BT * CD / 4);
    // qkv = x @ w_qkv + b_qkv
    convert_wT<<<dim3(3 * CD / 32, CD / 32), tblk>>>(w_qkv, wth, wtl, CD, 3 * CD);
    gemm_mma<<<dim3(3 * CD / 128, BT / 128), 256, GSM_BYTES>>>(
        a1h, a1l, wth, wtl, b_qkv, qkv, nullptr, nullptr, 3 * CD, CD, 0);
    // ctx (bf16 hi/lo, into a1)
    attn_kernel<<<dim3(TT / 64, NB * NH), 256>>>(qkv, a1h, a1l);
    // tmp = ctx @ w_out + b_out
    convert_wT<<<dim3(CD / 32, CD / 32), tblk>>>(w_out, wth, wtl, CD, CD);
    gemm_mma<<<dim3(CD / 128, BT / 128), 256, GSM_BYTES>>>(
        a1h, a1l, wth, wtl, b_out, tmp, nullptr, nullptr, CD, CD, 0);
    // x1 = LN(x + tmp), emit hi/lo into a1
    add_ln_kernel<<<BT, 256>>>(x, tmp, ln1g, ln1b, x1, a1h, a1l);
    // h = relu(x1 @ w1 + b1) -> bf16 hi/lo only
    convert_wT<<<dim3(FFD / 32, CD / 32), tblk>>>(w1, wth, wtl, CD, FFD);
    gemm_mma<<<dim3(FFD / 128, BT / 128), 256, GSM_BYTES>>>(
        a1h, a1l, wth, wtl, b1, nullptr, hh, hl, FFD, CD, 1);
    // tmp = h @ w2 + b2
    convert_wT<<<dim3(CD / 32, FFD / 32), tblk>>>(w2, wth, wtl, FFD, CD);
    gemm_mma<<<dim3(CD / 128, BT / 128), 256, GSM_BYTES>>>(
        hh, hl, wth, wtl, b2, tmp, nullptr, nullptr, CD, FFD, 0);
    // out = LN(x1 + tmp)
    add_ln_kernel<<<BT, 256>>>(x1, tmp, ln2g, ln2b, out, nullptr, nullptr);
}

// round 5
// speedup vs baseline: 4.5390x; 3.3784x over previous
#include <cuda_runtime.h>
#include <cuda_bf16.h>
#include <math.h>
#include <stdint.h>

#define NB 4
#define TT 2048
#define BT 8192      // NB*TT
#define CD 1024
#define FFD 4096
#define NH 16
#define DKD 64

// ---------------- scratch (device globals) ----------------
__device__ float g_qkv[BT * 3 * CD];                 // fp32
__device__ float g_tmp[BT * CD];
__device__ float g_x1 [BT * CD];
__device__ __nv_bfloat16 g_a1hi[BT * CD];            // activations (x / ctx / x1)
__device__ __nv_bfloat16 g_a1lo[BT * CD];
__device__ __nv_bfloat16 g_hhi [BT * FFD];           // FFN hidden
__device__ __nv_bfloat16 g_hlo [BT * FFD];
__device__ __nv_bfloat16 g_wthi[FFD * CD];           // transposed weights [N,K]
__device__ __nv_bfloat16 g_wtlo[FFD * CD];

__device__ __forceinline__ uint32_t smem_to_u32(const void* p) {
    uint32_t a;
    asm("{ .reg .u64 t; cvta.to.shared.u64 t, %1; cvt.u32.u64 %0, t; }" : "=r"(a) : "l"(p));
    return a;
}
#define CP_ASYNC16(sm, gp) \
    asm volatile("cp.async.cg.shared.global [%0], [%1], 16;" :: "r"(sm), "l"(gp))
#define CP_COMMIT() asm volatile("cp.async.commit_group;" ::: "memory")
#define CP_WAIT0()  asm volatile("cp.async.wait_group 0;" ::: "memory")
#define CP_WAIT1()  asm volatile("cp.async.wait_group 1;" ::: "memory")

__device__ __forceinline__ void ldm_x4(uint32_t* r, uint32_t addr) {
    asm volatile("ldmatrix.sync.aligned.m8n8.x4.shared.b16 {%0,%1,%2,%3}, [%4];"
        : "=r"(r[0]), "=r"(r[1]), "=r"(r[2]), "=r"(r[3]) : "r"(addr));
}
__device__ __forceinline__ void ldm_x4t(uint32_t* r, uint32_t addr) {
    asm volatile("ldmatrix.sync.aligned.m8n8.x4.trans.shared.b16 {%0,%1,%2,%3}, [%4];"
        : "=r"(r[0]), "=r"(r[1]), "=r"(r[2]), "=r"(r[3]) : "r"(addr));
}
__device__ __forceinline__ void mma_bf16(float* c, const uint32_t* a, const uint32_t* b) {
    asm volatile("mma.sync.aligned.m16n8k16.row.col.f32.bf16.bf16.f32 "
        "{%0,%1,%2,%3}, {%4,%5,%6,%7}, {%8,%9}, {%0,%1,%2,%3};"
        : "+f"(c[0]), "+f"(c[1]), "+f"(c[2]), "+f"(c[3])
        : "r"(a[0]), "r"(a[1]), "r"(a[2]), "r"(a[3]), "r"(b[0]), "r"(b[1]));
}

// ============================================================
// mma.sync bf16x3 GEMM: C[M,N] = A[M,K] @ B^T  (B stored [N,K])
// ============================================================
#define BKC 32
#define AST 40
#define OF_AH 0
#define OF_AL (128 * AST)
#define OF_BH (2 * 128 * AST)
#define OF_BL (3 * 128 * AST)
#define BUF_BYTES (4 * 128 * AST * 2)
#define GSM_BYTES (2 * BUF_BYTES)

__device__ __forceinline__ void load_chunk(uint32_t sbuf,
    const __nv_bfloat16* Ah, const __nv_bfloat16* Al,
    const __nv_bfloat16* Bh, const __nv_bfloat16* Bl,
    int K, int k0, int tid)
{
#pragma unroll
    for (int j = 0; j < 2; j++) {
        int v = tid + 256 * j;
        int row = v >> 2, c4 = v & 3;
        uint32_t doff = (uint32_t)(row * AST + c4 * 8) * 2;
        size_t goff = (size_t)row * K + k0 + c4 * 8;
        CP_ASYNC16(sbuf + OF_AH * 2 + doff, Ah + goff);
        CP_ASYNC16(sbuf + OF_AL * 2 + doff, Al + goff);
        CP_ASYNC16(sbuf + OF_BH * 2 + doff, Bh + goff);
        CP_ASYNC16(sbuf + OF_BL * 2 + doff, Bl + goff);
    }
}

__global__ __launch_bounds__(256)
void gemm_mma(const __nv_bfloat16* __restrict__ Ahi, const __nv_bfloat16* __restrict__ Alo,
              const __nv_bfloat16* __restrict__ Bhi, const __nv_bfloat16* __restrict__ Blo,
              const float* __restrict__ bias,
              float* __restrict__ Cf, __nv_bfloat16* __restrict__ Chi, __nv_bfloat16* __restrict__ Clo,
              int N, int K, int relu)
{
    extern __shared__ char dsm[];
    const uint32_t sb = smem_to_u32(dsm);
    const int tid = threadIdx.x;
    const int lane = tid & 31;
    const int w = tid >> 5;
    const int wm = w & 1, wn = w >> 1;
    const int bm0 = blockIdx.y * 128;
    const int bn0 = blockIdx.x * 128;

    const __nv_bfloat16* Ah = Ahi + (size_t)bm0 * K;
    const __nv_bfloat16* Al = Alo + (size_t)bm0 * K;
    const __nv_bfloat16* Bh = Bhi + (size_t)bn0 * K;
    const __nv_bfloat16* Bl = Blo + (size_t)bn0 * K;

    float acc[4][4][4];
#pragma unroll
    for (int a = 0; a < 4; a++)
#pragma unroll
        for (int b = 0; b < 4; b++)
#pragma unroll
            for (int c = 0; c < 4; c++) acc[a][b][c] = 0.f;

    const int arow = (lane & 7) + ((lane >> 3) & 1) * 8;
    const int acol = ((lane >> 4) & 1) * 8;
    const int brow = (lane & 7) + ((lane >> 4) & 1) * 8;
    const int bcol = ((lane >> 3) & 1) * 8;

    const int nch = K / BKC;
    load_chunk(sb, Ah, Al, Bh, Bl, K, 0, tid);
    CP_COMMIT();

    for (int i = 0; i < nch; i++) {
        if (i + 1 < nch) {
            load_chunk(sb + ((i + 1) & 1) * BUF_BYTES, Ah, Al, Bh, Bl, K, (i + 1) * BKC, tid);
            CP_COMMIT();
            CP_WAIT1();
        } else {
            CP_WAIT0();
        }
        __syncthreads();

        const uint32_t buf = sb + (i & 1) * BUF_BYTES;
#pragma unroll
        for (int kk = 0; kk < 2; kk++) {
            const int kb = kk * 16;
            uint32_t ah[4][4], al[4][4], bh[2][4], bl[2][4];
#pragma unroll
            for (int mt = 0; mt < 4; mt++) {
                int r = wm * 64 + mt * 16 + arow;
                uint32_t off = (uint32_t)(r * AST + kb + acol) * 2;
                ldm_x4(ah[mt], buf + OF_AH * 2 + off);
                ldm_x4(al[mt], buf + OF_AL * 2 + off);
            }
#pragma unroll
            for (int nt2 = 0; nt2 < 2; nt2++) {
                int r = wn * 32 + nt2 * 16 + brow;
                uint32_t off = (uint32_t)(r * AST + kb + bcol) * 2;
                ldm_x4(bh[nt2], buf + OF_BH * 2 + off);
                ldm_x4(bl[nt2], buf + OF_BL * 2 + off);
            }
#pragma unroll
            for (int mt = 0; mt < 4; mt++)
#pragma unroll
                for (int nt = 0; nt < 4; nt++) {
                    const uint32_t* fh = &bh[nt >> 1][(nt & 1) * 2];
                    const uint32_t* fl = &bl[nt >> 1][(nt & 1) * 2];
                    mma_bf16(acc[mt][nt], ah[mt], fh);
                    mma_bf16(acc[mt][nt], ah[mt], fl);
                    mma_bf16(acc[mt][nt], al[mt], fh);
                }
        }
        __syncthreads();
    }

    const int tr = lane >> 2, tc = (lane & 3) * 2;
    const int r0 = bm0 + wm * 64;
    const int c0 = bn0 + wn * 32;
#pragma unroll
    for (int mt = 0; mt < 4; mt++) {
#pragma unroll
        for (int nt = 0; nt < 4; nt++) {
            const int col = c0 + nt * 8 + tc;
            const float2 bv = *(const float2*)(bias + col);
#pragma unroll
            for (int h = 0; h < 2; h++) {
                const int row = r0 + mt * 16 + tr + h * 8;
                float v0 = acc[mt][nt][h * 2 + 0] + bv.x;
                float v1 = acc[mt][nt][h * 2 + 1] + bv.y;
                if (relu) { v0 = fmaxf(v0, 0.f); v1 = fmaxf(v1, 0.f); }
                if (Cf) {
                    float2 o = {v0, v1};
                    *(float2*)(Cf + (size_t)row * N + col) = o;
                }
                if (Chi) {
                    __nv_bfloat16 h0 = __float2bfloat16_rn(v0);
                    __nv_bfloat16 h1 = __float2bfloat16_rn(v1);
                    __nv_bfloat162 hp = __halves2bfloat162(h0, h1);
                    __nv_bfloat162 lp = __halves2bfloat162(
                        __float2bfloat16_rn(v0 - __bfloat162float(h0)),
                        __float2bfloat16_rn(v1 - __bfloat162float(h1)));
                    *(__nv_bfloat162*)(Chi + (size_t)row * N + col) = hp;
                    *(__nv_bfloat162*)(Clo + (size_t)row * N + col) = lp;
                }
            }
        }
    }
}

// ============================================================
// conversions
// ============================================================
__global__ __launch_bounds__(256) void convert_act(const float* __restrict__ in,
    __nv_bfloat16* __restrict__ ohi, __nv_bfloat16* __restrict__ olo, int n4)
{
    int i = blockIdx.x * 256 + threadIdx.x;
    if (i >= n4) return;
    float4 v = ((const float4*)in)[i];
    float vv[4] = {v.x, v.y, v.z, v.w};
    __nv_bfloat162 h[2], l[2];
#pragma unroll
    for (int u = 0; u < 2; u++) {
        __nv_bfloat16 h0 = __float2bfloat16_rn(vv[2 * u]);
        __nv_bfloat16 h1 = __float2bfloat16_rn(vv[2 * u + 1]);
        h[u] = __halves2bfloat162(h0, h1);
        l[u] = __halves2bfloat162(__float2bfloat16_rn(vv[2 * u] - __bfloat162float(h0)),
                                  __float2bfloat16_rn(vv[2 * u + 1] - __bfloat162float(h1)));
    }
    ((uint2*)ohi)[i] = *(uint2*)h;
    ((uint2*)olo)[i] = *(uint2*)l;
}

__global__ void convert_wT(const float* __restrict__ in,
    __nv_bfloat16* __restrict__ ohi, __nv_bfloat16* __restrict__ olo, int K, int N)
{
    __shared__ float t[32][33];
    int n0 = blockIdx.x * 32, k0 = blockIdx.y * 32;
    int tx = threadIdx.x, ty = threadIdx.y;
    for (int j = ty; j < 32; j += 8) t[j][tx] = in[(size_t)(k0 + j) * N + n0 + tx];
    __syncthreads();
    for (int j = ty; j < 32; j += 8) {
        float v = t[tx][j];
        __nv_bfloat16 h = __float2bfloat16_rn(v);
        size_t o = (size_t)(n0 + j) * K + k0 + tx;
        ohi[o] = h;
        olo[o] = __float2bfloat16_rn(v - __bfloat162float(h));
    }
}

// ============================================================
// Tensor-core flash attention (bf16 operands, fp32 accum).
// CTA: 128 queries of one (b,h); 4 warps x 32 rows; KV tiles of 64.
// ============================================================
__device__ __forceinline__ uint32_t asw(int row, int c8) {   // elem offset, 64-elem rows
    return (uint32_t)(row * 64 + (((c8) ^ (row & 7)) << 3));
}
__device__ __forceinline__ uint32_t packbf2(float a, float b) {
    __nv_bfloat162 t = __floats2bfloat162_rn(a, b);
    return *(uint32_t*)&t;
}

__global__ __launch_bounds__(128) void attn_mma(const float* __restrict__ qkv,
    __nv_bfloat16* __restrict__ chi, __nv_bfloat16* __restrict__ clo)
{
    __shared__ __nv_bfloat16 Qs[128 * 64];
    __shared__ __nv_bfloat16 Ks[64 * 64];
    __shared__ __nv_bfloat16 Vs[64 * 64];

    const int tid = threadIdx.x, lane = tid & 31, w = tid >> 5;
    const int b = blockIdx.y >> 4, h = blockIdx.y & 15;
    const int t0 = blockIdx.x * 128;
    const float* base = qkv + (size_t)b * TT * (3 * CD) + h * DKD;

    const uint32_t qsb = smem_to_u32(Qs);
    const uint32_t ksb = smem_to_u32(Ks);
    const uint32_t vsb = smem_to_u32(Vs);

    // load Q row `tid`, prescale by 1/8, convert to bf16 swizzled
    {
        const float* src = base + (size_t)(t0 + tid) * (3 * CD);
#pragma unroll
        for (int c8 = 0; c8 < 8; c8++) {
            float4 f0 = *(const float4*)(src + c8 * 8);
            float4 f1 = *(const float4*)(src + c8 * 8 + 4);
            uint4 o;
            o.x = packbf2(f0.x * 0.125f, f0.y * 0.125f);
            o.y = packbf2(f0.z * 0.125f, f0.w * 0.125f);
            o.z = packbf2(f1.x * 0.125f, f1.y * 0.125f);
            o.w = packbf2(f1.z * 0.125f, f1.w * 0.125f);
            *(uint4*)&Qs[asw(tid, c8)] = o;
        }
    }

    // fragment lane components
    const int arow = (lane & 15);
    const int ac8  = (lane >> 4);                       // A col-half
    const int brow = (lane & 7) + ((lane >> 4) & 1) * 8;
    const int bc8  = ((lane >> 3) & 1);                 // B k-half (non-trans)
    const int trow = (lane & 7) + ((lane >> 3) & 1) * 8;
    const int tc8  = ((lane >> 4) & 1);                 // V n-half (trans)
    const int tr = lane >> 2, tc = (lane & 3) * 2;

    float O[2][8][4];
#pragma unroll
    for (int mt = 0; mt < 2; mt++)
#pragma unroll
        for (int nt = 0; nt < 8; nt++)
#pragma unroll
            for (int c = 0; c < 4; c++) O[mt][nt][c] = 0.f;
    float mrow[2][2], lrow[2][2];
#pragma unroll
    for (int mt = 0; mt < 2; mt++) { mrow[mt][0] = mrow[mt][1] = -INFINITY; lrow[mt][0] = lrow[mt][1] = 0.f; }

    for (int kt = 0; kt < TT / 64; kt++) {
        __syncthreads();
        // load K/V tile: threads 0-63 -> K row, 64-127 -> V row
        {
            const int row = tid & 63;
            const float* src = base + (size_t)(kt * 64 + row) * (3 * CD) + ((tid < 64) ? CD : 2 * CD);
            __nv_bfloat16* dst = (tid < 64) ? Ks : Vs;
#pragma unroll
            for (int c8 = 0; c8 < 8; c8++) {
                float4 f0 = *(const float4*)(src + c8 * 8);
                float4 f1 = *(const float4*)(src + c8 * 8 + 4);
                uint4 o;
                o.x = packbf2(f0.x, f0.y); o.y = packbf2(f0.z, f0.w);
                o.z = packbf2(f1.x, f1.y); o.w = packbf2(f1.z, f1.w);
                *(uint4*)&dst[asw(row, c8)] = o;
            }
        }
        __syncthreads();

        // S = Q @ K^T
        float S[2][8][4];
#pragma unroll
        for (int mt = 0; mt < 2; mt++)
#pragma unroll
            for (int nt = 0; nt < 8; nt++)
#pragma unroll
                for (int c = 0; c < 4; c++) S[mt][nt][c] = 0.f;

#pragma unroll
        for (int kb = 0; kb < 4; kb++) {
            uint32_t qf[2][4];
#pragma unroll
            for (int mt = 0; mt < 2; mt++) {
                int r = w * 32 + mt * 16 + arow;
                ldm_x4(qf[mt], qsb + asw(r, kb * 2 + ac8) * 2);
            }
            uint32_t kf[4][4];
#pragma unroll
            for (int p = 0; p < 4; p++) {
                int r = p * 16 + brow;
                ldm_x4(kf[p], ksb + asw(r, kb * 2 + bc8) * 2);
            }
#pragma unroll
            for (int mt = 0; mt < 2; mt++)
#pragma unroll
                for (int nt = 0; nt < 8; nt++)
                    mma_bf16(S[mt][nt], qf[mt], &kf[nt >> 1][(nt & 1) * 2]);
        }

        // online softmax + pack P
        uint32_t pf[2][4][4];
#pragma unroll
        for (int mt = 0; mt < 2; mt++) {
            float mx0 = -INFINITY, mx1 = -INFINITY;
#pragma unroll
            for (int nt = 0; nt < 8; nt++) {
                mx0 = fmaxf(mx0, fmaxf(S[mt][nt][0], S[mt][nt][1]));
                mx1 = fmaxf(mx1, fmaxf(S[mt][nt][2], S[mt][nt][3]));
            }
            mx0 = fmaxf(mx0, __shfl_xor_sync(0xffffffffu, mx0, 1, 4));
            mx0 = fmaxf(mx0, __shfl_xor_sync(0xffffffffu, mx0, 2, 4));
            mx1 = fmaxf(mx1, __shfl_xor_sync(0xffffffffu, mx1, 1, 4));
            mx1 = fmaxf(mx1, __shfl_xor_sync(0xffffffffu, mx1, 2, 4));
            float mn0 = fmaxf(mrow[mt][0], mx0);
            float mn1 = fmaxf(mrow[mt][1], mx1);
            float a0 = __expf(mrow[mt][0] - mn0);
            float a1 = __expf(mrow[mt][1] - mn1);
            float ls0 = 0.f, ls1 = 0.f;
#pragma unroll
            for (int nt = 0; nt < 8; nt++) {
                float p0 = __expf(S[mt][nt][0] - mn0);
                float p1 = __expf(S[mt][nt][1] - mn0);
                float p2 = __expf(S[mt][nt][2] - mn1);
                float p3 = __expf(S[mt][nt][3] - mn1);
                ls0 += p0 + p1; ls1 += p2 + p3;
                S[mt][nt][0] = p0; S[mt][nt][1] = p1; S[mt][nt][2] = p2; S[mt][nt][3] = p3;
            }
            ls0 += __shfl_xor_sync(0xffffffffu, ls0, 1, 4);
            ls0 += __shfl_xor_sync(0xffffffffu, ls0, 2, 4);
            ls1 += __shfl_xor_sync(0xffffffffu, ls1, 1, 4);
            ls1 += __shfl_xor_sync(0xffffffffu, ls1, 2, 4);
            lrow[mt][0] = lrow[mt][0] * a0 + ls0;
            lrow[mt][1] = lrow[mt][1] * a1 + ls1;
            mrow[mt][0] = mn0; mrow[mt][1] = mn1;
#pragma unroll
            for (int nt = 0; nt < 8; nt++) {
                O[mt][nt][0] *= a0; O[mt][nt][1] *= a0;
                O[mt][nt][2] *= a1; O[mt][nt][3] *= a1;
            }
#pragma unroll
            for (int g = 0; g < 4; g++) {
                pf[mt][g][0] = packbf2(S[mt][2 * g][0], S[mt][2 * g][1]);
                pf[mt][g][1] = packbf2(S[mt][2 * g][2], S[mt][2 * g][3]);
                pf[mt][g][2] = packbf2(S[mt][2 * g + 1][0], S[mt][2 * g + 1][1]);
                pf[mt][g][3] = packbf2(S[mt][2 * g + 1][2], S[mt][2 * g + 1][3]);
            }
        }

        // O += P @ V
#pragma unroll
        for (int kb = 0; kb < 4; kb++) {
            uint32_t vf[4][4];
#pragma unroll
            for (int p = 0; p < 4; p++) {
                int r = kb * 16 + trow;
                ldm_x4t(vf[p], vsb + asw(r, p * 2 + tc8) * 2);
            }
#pragma unroll
            for (int mt = 0; mt < 2; mt++)
#pragma unroll
                for (int nt = 0; nt < 8; nt++)
                    mma_bf16(O[mt][nt], pf[mt][kb], &vf[nt >> 1][(nt & 1) * 2]);
        }
    }

    // epilogue: normalize, split hi/lo, store ctx
#pragma unroll
    for (int mt = 0; mt < 2; mt++) {
        float inv0 = 1.f / lrow[mt][0];
        float inv1 = 1.f / lrow[mt][1];
#pragma unroll
        for (int nt = 0; nt < 8; nt++) {
#pragma unroll
            for (int hr = 0; hr < 2; hr++) {
                float inv = hr ? inv1 : inv0;
                float v0 = O[mt][nt][hr * 2 + 0] * inv;
                float v1 = O[mt][nt][hr * 2 + 1] * inv;
                int row = t0 + w * 32 + mt * 16 + tr + hr * 8;
                size_t off = (size_t)(b * TT + row) * CD + h * DKD + nt * 8 + tc;
                __nv_bfloat16 h0 = __float2bfloat16_rn(v0);
                __nv_bfloat16 h1 = __float2bfloat16_rn(v1);
                __nv_bfloat162 hp = __halves2bfloat162(h0, h1);
                __nv_bfloat162 lp = __halves2bfloat162(
                    __float2bfloat16_rn(v0 - __bfloat162float(h0)),
                    __float2bfloat16_rn(v1 - __bfloat162float(h1)));
                *(__nv_bfloat162*)(chi + off) = hp;
                *(__nv_bfloat162*)(clo + off) = lp;
            }
        }
    }
}

// ============================================================
// out = LayerNorm(x + res); optional bf16 hi/lo emission
// ============================================================
__global__ __launch_bounds__(256) void add_ln_kernel(
    const float* __restrict__ x, const float* __restrict__ res,
    const float* __restrict__ gg, const float* __restrict__ bb,
    float* __restrict__ out, __nv_bfloat16* __restrict__ ohi, __nv_bfloat16* __restrict__ olo)
{
    const int row = blockIdx.x, tid = threadIdx.x;
    float4 xv = ((const float4*)(x + (size_t)row * CD))[tid];
    float4 rv = ((const float4*)(res + (size_t)row * CD))[tid];
    float y0 = xv.x + rv.x, y1 = xv.y + rv.y, y2 = xv.z + rv.z, y3 = xv.w + rv.w;
    float s = y0 + y1 + y2 + y3;
    float ss = y0 * y0 + y1 * y1 + y2 * y2 + y3 * y3;
#pragma unroll
    for (int off = 16; off; off >>= 1) {
        s  += __shfl_xor_sync(0xffffffffu, s, off);
        ss += __shfl_xor_sync(0xffffffffu, ss, off);
    }
    __shared__ float rs[8], rss[8];
    if ((tid & 31) == 0) { rs[tid >> 5] = s; rss[tid >> 5] = ss; }
    __syncthreads();
    float tot = 0.f, tots = 0.f;
#pragma unroll
    for (int i = 0; i < 8; i++) { tot += rs[i]; tots += rss[i]; }
    float mean = tot * (1.f / CD);
    float var = tots * (1.f / CD) - mean * mean;
    float iv = rsqrtf(var + 1e-5f);
    float4 gv = ((const float4*)gg)[tid];
    float4 bv = ((const float4*)bb)[tid];
    float wv[4];
    wv[0] = (y0 - mean) * iv * gv.x + bv.x;
    wv[1] = (y1 - mean) * iv * gv.y + bv.y;
    wv[2] = (y2 - mean) * iv * gv.z + bv.z;
    wv[3] = (y3 - mean) * iv * gv.w + bv.w;
    float4 ov = {wv[0], wv[1], wv[2], wv[3]};
    ((float4*)(out + (size_t)row * CD))[tid] = ov;
    if (ohi) {
        __nv_bfloat16 h0 = __float2bfloat16_rn(wv[0]), h1 = __float2bfloat16_rn(wv[1]);
        __nv_bfloat16 h2 = __float2bfloat16_rn(wv[2]), h3 = __float2bfloat16_rn(wv[3]);
        __nv_bfloat162 hp[2] = {__halves2bfloat162(h0, h1), __halves2bfloat162(h2, h3)};
        __nv_bfloat162 lp[2] = {
            __halves2bfloat162(__float2bfloat16_rn(wv[0] - __bfloat162float(h0)),
                               __float2bfloat16_rn(wv[1] - __bfloat162float(h1))),
            __halves2bfloat162(__float2bfloat16_rn(wv[2] - __bfloat162float(h2)),
                               __float2bfloat16_rn(wv[3] - __bfloat162float(h3)))};
        size_t off = (size_t)row * CD + tid * 4;
        *(uint2*)(ohi + off) = *(uint2*)hp;
        *(uint2*)(olo + off) = *(uint2*)lp;
    }
}

// ============================================================
extern "C" void kernel_launch(void* const* d_in, const int* in_sizes, int n_in,
                              void* d_out, int out_size)
{
    const float* x     = (const float*)d_in[0];
    const float* w_qkv = (const float*)d_in[1];
    const float* b_qkv = (const float*)d_in[2];
    const float* w_out = (const float*)d_in[3];
    const float* b_out = (const float*)d_in[4];
    const float* w1    = (const float*)d_in[5];
    const float* b1    = (const float*)d_in[6];
    const float* w2    = (const float*)d_in[7];
    const float* b2    = (const float*)d_in[8];
    const float* ln1g  = (const float*)d_in[9];
    const float* ln1b  = (const float*)d_in[10];
    const float* ln2g  = (const float*)d_in[11];
    const float* ln2b  = (const float*)d_in[12];
    float* out = (float*)d_out;

    float *qkv, *tmp, *x1;
    __nv_bfloat16 *a1h, *a1l, *hh, *hl, *wth, *wtl;
    cudaGetSymbolAddress((void**)&qkv, g_qkv);
    cudaGetSymbolAddress((void**)&tmp, g_tmp);
    cudaGetSymbolAddress((void**)&x1,  g_x1);
    cudaGetSymbolAddress((void**)&a1h, g_a1hi);
    cudaGetSymbolAddress((void**)&a1l, g_a1lo);
    cudaGetSymbolAddress((void**)&hh,  g_hhi);
    cudaGetSymbolAddress((void**)&hl,  g_hlo);
    cudaGetSymbolAddress((void**)&wth, g_wthi);
    cudaGetSymbolAddress((void**)&wtl, g_wtlo);

    cudaFuncSetAttribute(gemm_mma, cudaFuncAttributeMaxDynamicSharedMemorySize, GSM_BYTES);

    dim3 tblk(32, 8);

    convert_act<<<(BT * CD / 4 + 255) / 256, 256>>>(x, a1h, a1l, BT * CD / 4);
    convert_wT<<<dim3(3 * CD / 32, CD / 32), tblk>>>(w_qkv, wth, wtl, CD, 3 * CD);
    gemm_mma<<<dim3(3 * CD / 128, BT / 128), 256, GSM_BYTES>>>(
        a1h, a1l, wth, wtl, b_qkv, qkv, nullptr, nullptr, 3 * CD, CD, 0);
    attn_mma<<<dim3(TT / 128, NB * NH), 128>>>(qkv, a1h, a1l);
    convert_wT<<<dim3(CD / 32, CD / 32), tblk>>>(w_out, wth, wtl, CD, CD);
    gemm_mma<<<dim3(CD / 128, BT / 128), 256, GSM_BYTES>>>(
        a1h, a1l, wth, wtl, b_out, tmp, nullptr, nullptr, CD, CD, 0);
    add_ln_kernel<<<BT, 256>>>(x, tmp, ln1g, ln1b, x1, a1h, a1l);
    convert_wT<<<dim3(FFD / 32, CD / 32), tblk>>>(w1, wth, wtl, CD, FFD);
    gemm_mma<<<dim3(FFD / 128, BT / 128), 256, GSM_BYTES>>>(
        a1h, a1l, wth, wtl, b1, nullptr, hh, hl, FFD, CD, 1);
    convert_wT<<<dim3(CD / 32, FFD / 32), tblk>>>(w2, wth, wtl, FFD, CD);
    gemm_mma<<<dim3(CD / 128, BT / 128), 256, GSM_BYTES>>>(
        hh, hl, wth, wtl, b2, tmp, nullptr, nullptr, CD, FFD, 0);
    add_ln_kernel<<<BT, 256>>>(x1, tmp, ln2g, ln2b, out, nullptr, nullptr);
}

// round 7
// speedup vs baseline: 7.1872x; 1.5834x over previous
#include <cuda_runtime.h>
#include <cuda_fp16.h>
#include <math.h>
#include <stdint.h>

#define NB 4
#define TT 2048
#define BT 8192      // NB*TT
#define CD 1024
#define FFD 4096
#define NH 16
#define DKD 64

// ---------------- scratch (device globals) ----------------
__device__ __half g_qkvh[BT * 3 * CD];   // fp16 qkv
__device__ float  g_tmp [BT * CD];       // fp32 (attn_out / ffn_out)
__device__ float  g_x1  [BT * CD];       // fp32 post-LN1
__device__ __half g_ah  [BT * CD];       // fp16 activation (x, then x1)
__device__ __half g_ctxh[BT * CD];       // fp16 ctx
__device__ __half g_hh  [BT * FFD];      // fp16 FFN hidden
__device__ __half g_wth [FFD * CD];      // fp16 weight hi, transposed [N,K]
__device__ __half g_wtl [FFD * CD];      // fp16 weight lo

__device__ __forceinline__ uint32_t smem_to_u32(const void* p) {
    uint32_t a;
    asm("{ .reg .u64 t; cvta.to.shared.u64 t, %1; cvt.u32.u64 %0, t; }" : "=r"(a) : "l"(p));
    return a;
}
#define CP_ASYNC16(sm, gp) \
    asm volatile("cp.async.cg.shared.global [%0], [%1], 16;" :: "r"(sm), "l"(gp))
#define CP_COMMIT() asm volatile("cp.async.commit_group;" ::: "memory")
#define CP_WAIT0()  asm volatile("cp.async.wait_group 0;" ::: "memory")
#define CP_WAIT1()  asm volatile("cp.async.wait_group 1;" ::: "memory")

__device__ __forceinline__ void ldm_x4(uint32_t* r, uint32_t addr) {
    asm volatile("ldmatrix.sync.aligned.m8n8.x4.shared.b16 {%0,%1,%2,%3}, [%4];"
        : "=r"(r[0]), "=r"(r[1]), "=r"(r[2]), "=r"(r[3]) : "r"(addr));
}
__device__ __forceinline__ void ldm_x4t(uint32_t* r, uint32_t addr) {
    asm volatile("ldmatrix.sync.aligned.m8n8.x4.trans.shared.b16 {%0,%1,%2,%3}, [%4];"
        : "=r"(r[0]), "=r"(r[1]), "=r"(r[2]), "=r"(r[3]) : "r"(addr));
}
__device__ __forceinline__ void mma_f16(float* c, const uint32_t* a, const uint32_t* b) {
    asm volatile("mma.sync.aligned.m16n8k16.row.col.f32.f16.f16.f32 "
        "{%0,%1,%2,%3}, {%4,%5,%6,%7}, {%8,%9}, {%0,%1,%2,%3};"
        : "+f"(c[0]), "+f"(c[1]), "+f"(c[2]), "+f"(c[3])
        : "r"(a[0]), "r"(a[1]), "r"(a[2]), "r"(a[3]), "r"(b[0]), "r"(b[1]));
}
__device__ __forceinline__ uint32_t packh2(float a, float b) {
    __half2 t = __floats2half2_rn(a, b);
    return *(uint32_t*)&t;
}

// ============================================================
// fp16 GEMM: C[M,N] = A[M,K] @ B^T (B stored [N,K] hi/lo).
// NPASS=1: A*Bh ; NPASS=2: A*Bh + A*Bl.
// 128x128 tile, BK=32, 8 warps x (64x32), cp.async double buffer.
// ============================================================
#define BKC 32
#define AST 40                       // halves per smem row (80B) - conflict-free ldmatrix
#define TILE_B2 (128 * AST * 2)      // 10240 B per tile

template<int NPASS>
__device__ __forceinline__ void load_chunk(uint32_t sbuf,
    const __half* A, const __half* Bh, const __half* Bl, int K, int k0, int tid)
{
#pragma unroll
    for (int j = 0; j < 2; j++) {
        int v = tid + 256 * j;
        int row = v >> 2, c8 = v & 3;
        uint32_t doff = (uint32_t)(row * AST + c8 * 8) * 2;
        size_t goff = (size_t)row * K + k0 + c8 * 8;
        CP_ASYNC16(sbuf + doff, A + goff);
        CP_ASYNC16(sbuf + TILE_B2 + doff, Bh + goff);
        if (NPASS == 2) CP_ASYNC16(sbuf + 2 * TILE_B2 + doff, Bl + goff);
    }
}

template<int NPASS>
__global__ __launch_bounds__(256)
void gemm_mma(const __half* __restrict__ A0, const __half* __restrict__ Bh0,
              const __half* __restrict__ Bl0, const float* __restrict__ bias,
              float* __restrict__ Cf, __half* __restrict__ Ch,
              int N, int K, int relu)
{
    extern __shared__ char dsm[];
    const uint32_t sb = smem_to_u32(dsm);
    const uint32_t BUFB = (1 + NPASS) * TILE_B2;
    const int tid = threadIdx.x;
    const int lane = tid & 31;
    const int w = tid >> 5;
    const int wm = w & 1, wn = w >> 1;
    const int bm0 = blockIdx.y * 128;
    const int bn0 = blockIdx.x * 128;

    const __half* A  = A0  + (size_t)bm0 * K;
    const __half* Bh = Bh0 + (size_t)bn0 * K;
    const __half* Bl = (NPASS == 2) ? Bl0 + (size_t)bn0 * K : Bh;

    float acc[4][4][4];
#pragma unroll
    for (int a = 0; a < 4; a++)
#pragma unroll
        for (int b = 0; b < 4; b++)
#pragma unroll
            for (int c = 0; c < 4; c++) acc[a][b][c] = 0.f;

    const int arow = (lane & 7) + ((lane >> 3) & 1) * 8;
    const int acol = ((lane >> 4) & 1) * 8;
    const int brow = (lane & 7) + ((lane >> 4) & 1) * 8;
    const int bcol = ((lane >> 3) & 1) * 8;

    const int nch = K / BKC;
    load_chunk<NPASS>(sb, A, Bh, Bl, K, 0, tid);
    CP_COMMIT();

    for (int i = 0; i < nch; i++) {
        if (i + 1 < nch) {
            load_chunk<NPASS>(sb + ((i + 1) & 1) * BUFB, A, Bh, Bl, K, (i + 1) * BKC, tid);
            CP_COMMIT();
            CP_WAIT1();
        } else {
            CP_WAIT0();
        }
        __syncthreads();

        const uint32_t buf = sb + (i & 1) * BUFB;
#pragma unroll
        for (int kk = 0; kk < 2; kk++) {
            const int kb = kk * 16;
            uint32_t af[4][4], bh[2][4], bl[2][4];
#pragma unroll
            for (int mt = 0; mt < 4; mt++) {
                int r = wm * 64 + mt * 16 + arow;
                ldm_x4(af[mt], buf + (uint32_t)(r * AST + kb + acol) * 2);
            }
#pragma unroll
            for (int nt2 = 0; nt2 < 2; nt2++) {
                int r = wn * 32 + nt2 * 16 + brow;
                uint32_t off = (uint32_t)(r * AST + kb + bcol) * 2;
                ldm_x4(bh[nt2], buf + TILE_B2 + off);
                if (NPASS == 2) ldm_x4(bl[nt2], buf + 2 * TILE_B2 + off);
            }
#pragma unroll
            for (int mt = 0; mt < 4; mt++)
#pragma unroll
                for (int nt = 0; nt < 4; nt++) {
                    mma_f16(acc[mt][nt], af[mt], &bh[nt >> 1][(nt & 1) * 2]);
                    if (NPASS == 2)
                        mma_f16(acc[mt][nt], af[mt], &bl[nt >> 1][(nt & 1) * 2]);
                }
        }
        __syncthreads();
    }

    const int tr = lane >> 2, tc = (lane & 3) * 2;
    const int r0 = bm0 + wm * 64;
    const int c0 = bn0 + wn * 32;
#pragma unroll
    for (int mt = 0; mt < 4; mt++) {
#pragma unroll
        for (int nt = 0; nt < 4; nt++) {
            const int col = c0 + nt * 8 + tc;
            const float2 bv = *(const float2*)(bias + col);
#pragma unroll
            for (int h = 0; h < 2; h++) {
                const int row = r0 + mt * 16 + tr + h * 8;
                float v0 = acc[mt][nt][h * 2 + 0] + bv.x;
                float v1 = acc[mt][nt][h * 2 + 1] + bv.y;
                if (relu) { v0 = fmaxf(v0, 0.f); v1 = fmaxf(v1, 0.f); }
                if (Cf) {
                    float2 o = {v0, v1};
                    *(float2*)(Cf + (size_t)row * N + col) = o;
                } else {
                    *(uint32_t*)(Ch + (size_t)row * N + col) = packh2(v0, v1);
                }
            }
        }
    }
}

// ============================================================
// conversions
// ============================================================
__global__ __launch_bounds__(256) void convert_h(const float* __restrict__ in,
    __half* __restrict__ oh, int n8)
{
    int i = blockIdx.x * 256 + threadIdx.x;
    if (i >= n8) return;
    float4 a = ((const float4*)in)[2 * i];
    float4 b = ((const float4*)in)[2 * i + 1];
    uint4 o;
    o.x = packh2(a.x, a.y); o.y = packh2(a.z, a.w);
    o.z = packh2(b.x, b.y); o.w = packh2(b.z, b.w);
    ((uint4*)oh)[i] = o;
}

// weight [K,N] fp32 -> [N,K] fp16 hi (+ optional lo)
__global__ void convert_wT(const float* __restrict__ in,
    __half* __restrict__ ohi, __half* __restrict__ olo, int K, int N)
{
    __shared__ float t[32][33];
    int n0 = blockIdx.x * 32, k0 = blockIdx.y * 32;
    int tx = threadIdx.x, ty = threadIdx.y;
    for (int j = ty; j < 32; j += 8) t[j][tx] = in[(size_t)(k0 + j) * N + n0 + tx];
    __syncthreads();
    for (int j = ty; j < 32; j += 8) {
        float v = t[tx][j];
        __half h = __float2half_rn(v);
        size_t o = (size_t)(n0 + j) * K + k0 + tx;
        ohi[o] = h;
        if (olo) olo[o] = __float2half_rn(v - __half2float(h));
    }
}

// ============================================================
// fp16 tensor-core flash attention. CTA: 128 queries of one (b,h).
// 4 warps x 32 rows; KV tiles of 64; fp32 accum; ctx out fp16.
// ============================================================
__device__ __forceinline__ uint32_t asw(int row, int c8) {   // elem offset, 64-elem rows
    return (uint32_t)(row * 64 + (((c8) ^ (row & 7)) << 3));
}

__global__ __launch_bounds__(128) void attn_mma(const __half* __restrict__ qkv,
    __half* __restrict__ ctx)
{
    __shared__ __half Qs[128 * 64];
    __shared__ __half Ks[64 * 64];
    __shared__ __half Vs[64 * 64];

    const int tid = threadIdx.x, lane = tid & 31, w = tid >> 5;
    const int b = blockIdx.y >> 4, h = blockIdx.y & 15;
    const int t0 = blockIdx.x * 128;
    const __half* base = qkv + (size_t)b * TT * (3 * CD) + h * DKD;

    const uint32_t qsb = smem_to_u32(Qs);
    const uint32_t ksb = smem_to_u32(Ks);
    const uint32_t vsb = smem_to_u32(Vs);

    // load Q row `tid` (fp16), prescale by 1/8 (exact), swizzle
    {
        const __half* src = base + (size_t)(t0 + tid) * (3 * CD);
        const __half2 sc = __float2half2_rn(0.125f);
#pragma unroll
        for (int c8 = 0; c8 < 8; c8++) {
            uint4 d = *(const uint4*)(src + c8 * 8);
            __half2* p = (__half2*)&d;
#pragma unroll
            for (int u = 0; u < 4; u++) p[u] = __hmul2(p[u], sc);
            *(uint4*)&Qs[asw(tid, c8)] = d;
        }
    }

    const int arow = (lane & 15);
    const int ac8  = (lane >> 4);
    const int brow = (lane & 7) + ((lane >> 4) & 1) * 8;
    const int bc8  = ((lane >> 3) & 1);
    const int trow = (lane & 7) + ((lane >> 3) & 1) * 8;
    const int tc8  = ((lane >> 4) & 1);
    const int tr = lane >> 2, tc = (lane & 3) * 2;

    float O[2][8][4];
#pragma unroll
    for (int mt = 0; mt < 2; mt++)
#pragma unroll
        for (int nt = 0; nt < 8; nt++)
#pragma unroll
            for (int c = 0; c < 4; c++) O[mt][nt][c] = 0.f;
    float mrow[2][2], lrow[2][2];
#pragma unroll
    for (int mt = 0; mt < 2; mt++) { mrow[mt][0] = mrow[mt][1] = -INFINITY; lrow[mt][0] = lrow[mt][1] = 0.f; }

    for (int kt = 0; kt < TT / 64; kt++) {
        __syncthreads();
        {
            const int row = tid & 63;
            const __half* src = base + (size_t)(kt * 64 + row) * (3 * CD) + ((tid < 64) ? CD : 2 * CD);
            __half* dst = (tid < 64) ? Ks : Vs;
#pragma unroll
            for (int c8 = 0; c8 < 8; c8++)
                *(uint4*)&dst[asw(row, c8)] = *(const uint4*)(src + c8 * 8);
        }
        __syncthreads();

        // S = Q @ K^T
        float S[2][8][4];
#pragma unroll
        for (int mt = 0; mt < 2; mt++)
#pragma unroll
            for (int nt = 0; nt < 8; nt++)
#pragma unroll
                for (int c = 0; c < 4; c++) S[mt][nt][c] = 0.f;

#pragma unroll
        for (int kb = 0; kb < 4; kb++) {
            uint32_t qf[2][4];
#pragma unroll
            for (int mt = 0; mt < 2; mt++) {
                int r = w * 32 + mt * 16 + arow;
                ldm_x4(qf[mt], qsb + asw(r, kb * 2 + ac8) * 2);
            }
            uint32_t kf[4][4];
#pragma unroll
            for (int p = 0; p < 4; p++) {
                int r = p * 16 + brow;
                ldm_x4(kf[p], ksb + asw(r, kb * 2 + bc8) * 2);
            }
#pragma unroll
            for (int mt = 0; mt < 2; mt++)
#pragma unroll
                for (int nt = 0; nt < 8; nt++)
                    mma_f16(S[mt][nt], qf[mt], &kf[nt >> 1][(nt & 1) * 2]);
        }

        // online softmax + pack P (fp16)
        uint32_t pf[2][4][4];
#pragma unroll
        for (int mt = 0; mt < 2; mt++) {
            float mx0 = -INFINITY, mx1 = -INFINITY;
#pragma unroll
            for (int nt = 0; nt < 8; nt++) {
                mx0 = fmaxf(mx0, fmaxf(S[mt][nt][0], S[mt][nt][1]));
                mx1 = fmaxf(mx1, fmaxf(S[mt][nt][2], S[mt][nt][3]));
            }
            mx0 = fmaxf(mx0, __shfl_xor_sync(0xffffffffu, mx0, 1, 4));
            mx0 = fmaxf(mx0, __shfl_xor_sync(0xffffffffu, mx0, 2, 4));
            mx1 = fmaxf(mx1, __shfl_xor_sync(0xffffffffu, mx1, 1, 4));
            mx1 = fmaxf(mx1, __shfl_xor_sync(0xffffffffu, mx1, 2, 4));
            float mn0 = fmaxf(mrow[mt][0], mx0);
            float mn1 = fmaxf(mrow[mt][1], mx1);
            float a0 = __expf(mrow[mt][0] - mn0);
            float a1 = __expf(mrow[mt][1] - mn1);
            float ls0 = 0.f, ls1 = 0.f;
#pragma unroll
            for (int nt = 0; nt < 8; nt++) {
                float p0 = __expf(S[mt][nt][0] - mn0);
                float p1 = __expf(S[mt][nt][1] - mn0);
                float p2 = __expf(S[mt][nt][2] - mn1);
                float p3 = __expf(S[mt][nt][3] - mn1);
                ls0 += p0 + p1; ls1 += p2 + p3;
                S[mt][nt][0] = p0; S[mt][nt][1] = p1; S[mt][nt][2] = p2; S[mt][nt][3] = p3;
            }
            ls0 += __shfl_xor_sync(0xffffffffu, ls0, 1, 4);
            ls0 += __shfl_xor_sync(0xffffffffu, ls0, 2, 4);
            ls1 += __shfl_xor_sync(0xffffffffu, ls1, 1, 4);
            ls1 += __shfl_xor_sync(0xffffffffu, ls1, 2, 4);
            lrow[mt][0] = lrow[mt][0] * a0 + ls0;
            lrow[mt][1] = lrow[mt][1] * a1 + ls1;
            mrow[mt][0] = mn0; mrow[mt][1] = mn1;
#pragma unroll
            for (int nt = 0; nt < 8; nt++) {
                O[mt][nt][0] *= a0; O[mt][nt][1] *= a0;
                O[mt][nt][2] *= a1; O[mt][nt][3] *= a1;
            }
#pragma unroll
            for (int g = 0; g < 4; g++) {
                pf[mt][g][0] = packh2(S[mt][2 * g][0], S[mt][2 * g][1]);
                pf[mt][g][1] = packh2(S[mt][2 * g][2], S[mt][2 * g][3]);
                pf[mt][g][2] = packh2(S[mt][2 * g + 1][0], S[mt][2 * g + 1][1]);
                pf[mt][g][3] = packh2(S[mt][2 * g + 1][2], S[mt][2 * g + 1][3]);
            }
        }

        // O += P @ V
#pragma unroll
        for (int kb = 0; kb < 4; kb++) {
            uint32_t vf[4][4];
#pragma unroll
            for (int p = 0; p < 4; p++) {
                int r = kb * 16 + trow;
                ldm_x4t(vf[p], vsb + asw(r, p * 2 + tc8) * 2);
            }
#pragma unroll
            for (int mt = 0; mt < 2; mt++)
#pragma unroll
                for (int nt = 0; nt < 8; nt++)
                    mma_f16(O[mt][nt], pf[mt][kb], &vf[nt >> 1][(nt & 1) * 2]);
        }
    }

    // epilogue: normalize, store ctx fp16
#pragma unroll
    for (int mt = 0; mt < 2; mt++) {
        float inv0 = 1.f / lrow[mt][0];
        float inv1 = 1.f / lrow[mt][1];
#pragma unroll
        for (int nt = 0; nt < 8; nt++) {
#pragma unroll
            for (int hr = 0; hr < 2; hr++) {
                float inv = hr ? inv1 : inv0;
                float v0 = O[mt][nt][hr * 2 + 0] * inv;
                float v1 = O[mt][nt][hr * 2 + 1] * inv;
                int row = t0 + w * 32 + mt * 16 + tr + hr * 8;
                size_t off = (size_t)(b * TT + row) * CD + h * DKD + nt * 8 + tc;
                *(uint32_t*)(ctx + off) = packh2(v0, v1);
            }
        }
    }
}

// ============================================================
// out = LayerNorm(x + res); optional fp16 emission
// ============================================================
__global__ __launch_bounds__(256) void add_ln_kernel(
    const float* __restrict__ x, const float* __restrict__ res,
    const float* __restrict__ gg, const float* __restrict__ bb,
    float* __restrict__ out, __half* __restrict__ oh)
{
    const int row = blockIdx.x, tid = threadIdx.x;
    float4 xv = ((const float4*)(x + (size_t)row * CD))[tid];
    float4 rv = ((const float4*)(res + (size_t)row * CD))[tid];
    float y0 = xv.x + rv.x, y1 = xv.y + rv.y, y2 = xv.z + rv.z, y3 = xv.w + rv.w;
    float s = y0 + y1 + y2 + y3;
    float ss = y0 * y0 + y1 * y1 + y2 * y2 + y3 * y3;
#pragma unroll
    for (int off = 16; off; off >>= 1) {
        s  += __shfl_xor_sync(0xffffffffu, s, off);
        ss += __shfl_xor_sync(0xffffffffu, ss, off);
    }
    __shared__ float rs[8], rss[8];
    if ((tid & 31) == 0) { rs[tid >> 5] = s; rss[tid >> 5] = ss; }
    __syncthreads();
    float tot = 0.f, tots = 0.f;
#pragma unroll
    for (int i = 0; i < 8; i++) { tot += rs[i]; tots += rss[i]; }
    float mean = tot * (1.f / CD);
    float var = tots * (1.f / CD) - mean * mean;
    float iv = rsqrtf(var + 1e-5f);
    float4 gv = ((const float4*)gg)[tid];
    float4 bv = ((const float4*)bb)[tid];
    float w0 = (y0 - mean) * iv * gv.x + bv.x;
    float w1 = (y1 - mean) * iv * gv.y + bv.y;
    float w2 = (y2 - mean) * iv * gv.z + bv.z;
    float w3 = (y3 - mean) * iv * gv.w + bv.w;
    float4 ov = {w0, w1, w2, w3};
    ((float4*)(out + (size_t)row * CD))[tid] = ov;
    if (oh) {
        uint2 o;
        o.x = packh2(w0, w1);
        o.y = packh2(w2, w3);
        *(uint2*)(oh + (size_t)row * CD + tid * 4) = o;
    }
}

// ============================================================
extern "C" void kernel_launch(void* const* d_in, const int* in_sizes, int n_in,
                              void* d_out, int out_size)
{
    const float* x     = (const float*)d_in[0];
    const float* w_qkv = (const float*)d_in[1];
    const float* b_qkv = (const float*)d_in[2];
    const float* w_out = (const float*)d_in[3];
    const float* b_out = (const float*)d_in[4];
    const float* w1    = (const float*)d_in[5];
    const float* b1    = (const float*)d_in[6];
    const float* w2    = (const float*)d_in[7];
    const float* b2    = (const float*)d_in[8];
    const float* ln1g  = (const float*)d_in[9];
    const float* ln1b  = (const float*)d_in[10];
    const float* ln2g  = (const float*)d_in[11];
    const float* ln2b  = (const float*)d_in[12];
    float* out = (float*)d_out;

    float *tmp, *x1;
    __half *qkvh, *ah, *ctxh, *hh, *wth, *wtl;
    cudaGetSymbolAddress((void**)&qkvh, g_qkvh);
    cudaGetSymbolAddress((void**)&tmp,  g_tmp);
    cudaGetSymbolAddress((void**)&x1,   g_x1);
    cudaGetSymbolAddress((void**)&ah,   g_ah);
    cudaGetSymbolAddress((void**)&ctxh, g_ctxh);
    cudaGetSymbolAddress((void**)&hh,   g_hh);
    cudaGetSymbolAddress((void**)&wth,  g_wth);
    cudaGetSymbolAddress((void**)&wtl,  g_wtl);

    const int GSM1 = 2 * 2 * TILE_B2;    // 40960
    const int GSM2 = 2 * 3 * TILE_B2;    // 61440
    cudaFuncSetAttribute(gemm_mma<1>, cudaFuncAttributeMaxDynamicSharedMemorySize, GSM1);
    cudaFuncSetAttribute(gemm_mma<2>, cudaFuncAttributeMaxDynamicSharedMemorySize, GSM2);

    dim3 tblk(32, 8);

    // x -> fp16
    convert_h<<<(BT * CD / 8 + 255) / 256, 256>>>(x, ah, BT * CD / 8);
    // qkv = x @ w_qkv + b_qkv  (1-pass, out fp16)
    convert_wT<<<dim3(3 * CD / 32, CD / 32), tblk>>>(w_qkv, wth, nullptr, CD, 3 * CD);
    gemm_mma<1><<<dim3(3 * CD / 128, BT / 128), 256, GSM1>>>(
        ah, wth, nullptr, b_qkv, nullptr, qkvh, 3 * CD, CD, 0);
    // ctx = attention(qkv) -> fp16
    attn_mma<<<dim3(TT / 128, NB * NH), 128>>>(qkvh, ctxh);
    // attn_out = ctx @ w_out + b_out (1-pass, out fp32)
    convert_wT<<<dim3(CD / 32, CD / 32), tblk>>>(w_out, wth, nullptr, CD, CD);
    gemm_mma<1><<<dim3(CD / 128, BT / 128), 256, GSM1>>>(
        ctxh, wth, nullptr, b_out, tmp, nullptr, CD, CD, 0);
    // x1 = LN(x + attn_out), emit fp16 into ah
    add_ln_kernel<<<BT, 256>>>(x, tmp, ln1g, ln1b, x1, ah);
    // h = relu(x1 @ w1 + b1) (2-pass, out fp16)
    convert_wT<<<dim3(FFD / 32, CD / 32), tblk>>>(w1, wth, wtl, CD, FFD);
    gemm_mma<2><<<dim3(FFD / 128, BT / 128), 256, GSM2>>>(
        ah, wth, wtl, b1, nullptr, hh, FFD, CD, 1);
    // ffn_out = h @ w2 + b2 (2-pass, out fp32)
    convert_wT<<<dim3(CD / 32, FFD / 32), tblk>>>(w2, wth, wtl, FFD, CD);
    gemm_mma<2><<<dim3(CD / 128, BT / 128), 256, GSM2>>>(
        hh, wth, wtl, b2, tmp, nullptr, CD, FFD, 0);
    // out = LN(x1 + ffn_out)
    add_ln_kernel<<<BT, 256>>>(x1, tmp, ln2g, ln2b, out, nullptr);
}

// round 8
// speedup vs baseline: 8.0172x; 1.1155x over previous
#include <cuda_runtime.h>
#include <cuda_fp16.h>
#include <math.h>
#include <stdint.h>

#define NB 4
#define TT 2048
#define BT 8192      // NB*TT
#define CD 1024
#define FFD 4096
#define NH 16
#define DKD 64

// ---------------- scratch (device globals) ----------------
__device__ __half g_qkvh[BT * 3 * CD];   // fp16 qkv
__device__ float  g_tmp [BT * CD];       // fp32 (attn_out / ffn_out)
__device__ float  g_x1  [BT * CD];       // fp32 post-LN1
__device__ __half g_ah  [BT * CD];       // fp16 activation (x, then x1)
__device__ __half g_ctxh[BT * CD];       // fp16 ctx
__device__ __half g_hh  [BT * FFD];      // fp16 FFN hidden
__device__ __half g_wth [FFD * CD];      // fp16 weight, transposed [N,K]

__device__ __forceinline__ uint32_t smem_to_u32(const void* p) {
    uint32_t a;
    asm("{ .reg .u64 t; cvta.to.shared.u64 t, %1; cvt.u32.u64 %0, t; }" : "=r"(a) : "l"(p));
    return a;
}
#define CP_ASYNC16(sm, gp) \
    asm volatile("cp.async.cg.shared.global [%0], [%1], 16;" :: "r"(sm), "l"(gp))
#define CP_COMMIT() asm volatile("cp.async.commit_group;" ::: "memory")
#define CP_WAIT0()  asm volatile("cp.async.wait_group 0;" ::: "memory")
#define CP_WAIT1()  asm volatile("cp.async.wait_group 1;" ::: "memory")

__device__ __forceinline__ void ldm_x4(uint32_t* r, uint32_t addr) {
    asm volatile("ldmatrix.sync.aligned.m8n8.x4.shared.b16 {%0,%1,%2,%3}, [%4];"
        : "=r"(r[0]), "=r"(r[1]), "=r"(r[2]), "=r"(r[3]) : "r"(addr));
}
__device__ __forceinline__ void ldm_x4t(uint32_t* r, uint32_t addr) {
    asm volatile("ldmatrix.sync.aligned.m8n8.x4.trans.shared.b16 {%0,%1,%2,%3}, [%4];"
        : "=r"(r[0]), "=r"(r[1]), "=r"(r[2]), "=r"(r[3]) : "r"(addr));
}
__device__ __forceinline__ void mma_f16(float* c, const uint32_t* a, const uint32_t* b) {
    asm volatile("mma.sync.aligned.m16n8k16.row.col.f32.f16.f16.f32 "
        "{%0,%1,%2,%3}, {%4,%5,%6,%7}, {%8,%9}, {%0,%1,%2,%3};"
        : "+f"(c[0]), "+f"(c[1]), "+f"(c[2]), "+f"(c[3])
        : "r"(a[0]), "r"(a[1]), "r"(a[2]), "r"(a[3]), "r"(b[0]), "r"(b[1]));
}
__device__ __forceinline__ uint32_t packh2(float a, float b) {
    __half2 t = __floats2half2_rn(a, b);
    return *(uint32_t*)&t;
}

// ============================================================
// fp16 GEMM: C[M,N] = A[M,K] @ B^T (B stored [N,K]).
// 128x128 tile, BK=32, 8 warps x (64x32), cp.async double buffer.
// ============================================================
#define BKC 32
#define AST 40                       // halves per smem row (80B) - conflict-free ldmatrix
#define TILE_B2 (128 * AST * 2)      // 10240 B per tile
#define BUFB (2 * TILE_B2)           // A + B
#define GSM_BYTES (2 * BUFB)         // double buffered: 40960

__device__ __forceinline__ void load_chunk(uint32_t sbuf,
    const __half* A, const __half* B, int K, int k0, int tid)
{
#pragma unroll
    for (int j = 0; j < 2; j++) {
        int v = tid + 256 * j;
        int row = v >> 2, c8 = v & 3;
        uint32_t doff = (uint32_t)(row * AST + c8 * 8) * 2;
        size_t goff = (size_t)row * K + k0 + c8 * 8;
        CP_ASYNC16(sbuf + doff, A + goff);
        CP_ASYNC16(sbuf + TILE_B2 + doff, B + goff);
    }
}

__global__ __launch_bounds__(256)
void gemm_mma(const __half* __restrict__ A0, const __half* __restrict__ B0,
              const float* __restrict__ bias,
              float* __restrict__ Cf, __half* __restrict__ Ch,
              int N, int K, int relu)
{
    extern __shared__ char dsm[];
    const uint32_t sb = smem_to_u32(dsm);
    const int tid = threadIdx.x;
    const int lane = tid & 31;
    const int w = tid >> 5;
    const int wm = w & 1, wn = w >> 1;
    const int bm0 = blockIdx.y * 128;
    const int bn0 = blockIdx.x * 128;

    const __half* A = A0 + (size_t)bm0 * K;
    const __half* B = B0 + (size_t)bn0 * K;

    float acc[4][4][4];
#pragma unroll
    for (int a = 0; a < 4; a++)
#pragma unroll
        for (int b = 0; b < 4; b++)
#pragma unroll
            for (int c = 0; c < 4; c++) acc[a][b][c] = 0.f;

    const int arow = (lane & 7) + ((lane >> 3) & 1) * 8;
    const int acol = ((lane >> 4) & 1) * 8;
    const int brow = (lane & 7) + ((lane >> 4) & 1) * 8;
    const int bcol = ((lane >> 3) & 1) * 8;

    const int nch = K / BKC;
    load_chunk(sb, A, B, K, 0, tid);
    CP_COMMIT();

    for (int i = 0; i < nch; i++) {
        if (i + 1 < nch) {
            load_chunk(sb + ((i + 1) & 1) * BUFB, A, B, K, (i + 1) * BKC, tid);
            CP_COMMIT();
            CP_WAIT1();
        } else {
            CP_WAIT0();
        }
        __syncthreads();

        const uint32_t buf = sb + (i & 1) * BUFB;
#pragma unroll
        for (int kk = 0; kk < 2; kk++) {
            const int kb = kk * 16;
            uint32_t af[4][4], bf[2][4];
#pragma unroll
            for (int mt = 0; mt < 4; mt++) {
                int r = wm * 64 + mt * 16 + arow;
                ldm_x4(af[mt], buf + (uint32_t)(r * AST + kb + acol) * 2);
            }
#pragma unroll
            for (int nt2 = 0; nt2 < 2; nt2++) {
                int r = wn * 32 + nt2 * 16 + brow;
                ldm_x4(bf[nt2], buf + TILE_B2 + (uint32_t)(r * AST + kb + bcol) * 2);
            }
#pragma unroll
            for (int mt = 0; mt < 4; mt++)
#pragma unroll
                for (int nt = 0; nt < 4; nt++)
                    mma_f16(acc[mt][nt], af[mt], &bf[nt >> 1][(nt & 1) * 2]);
        }
        __syncthreads();
    }

    const int tr = lane >> 2, tc = (lane & 3) * 2;
    const int r0 = bm0 + wm * 64;
    const int c0 = bn0 + wn * 32;
#pragma unroll
    for (int mt = 0; mt < 4; mt++) {
#pragma unroll
        for (int nt = 0; nt < 4; nt++) {
            const int col = c0 + nt * 8 + tc;
            const float2 bv = *(const float2*)(bias + col);
#pragma unroll
            for (int h = 0; h < 2; h++) {
                const int row = r0 + mt * 16 + tr + h * 8;
                float v0 = acc[mt][nt][h * 2 + 0] + bv.x;
                float v1 = acc[mt][nt][h * 2 + 1] + bv.y;
                if (relu) { v0 = fmaxf(v0, 0.f); v1 = fmaxf(v1, 0.f); }
                if (Cf) {
                    float2 o = {v0, v1};
                    *(float2*)(Cf + (size_t)row * N + col) = o;
                } else {
                    *(uint32_t*)(Ch + (size_t)row * N + col) = packh2(v0, v1);
                }
            }
        }
    }
}

// ============================================================
// conversions
// ============================================================
__global__ __launch_bounds__(256) void convert_h(const float* __restrict__ in,
    __half* __restrict__ oh, int n8)
{
    int i = blockIdx.x * 256 + threadIdx.x;
    if (i >= n8) return;
    float4 a = ((const float4*)in)[2 * i];
    float4 b = ((const float4*)in)[2 * i + 1];
    uint4 o;
    o.x = packh2(a.x, a.y); o.y = packh2(a.z, a.w);
    o.z = packh2(b.x, b.y); o.w = packh2(b.z, b.w);
    ((uint4*)oh)[i] = o;
}

// weight [K,N] fp32 -> [N,K] fp16 (transpose)
__global__ void convert_wT(const float* __restrict__ in,
    __half* __restrict__ ohi, int K, int N)
{
    __shared__ float t[32][33];
    int n0 = blockIdx.x * 32, k0 = blockIdx.y * 32;
    int tx = threadIdx.x, ty = threadIdx.y;
    for (int j = ty; j < 32; j += 8) t[j][tx] = in[(size_t)(k0 + j) * N + n0 + tx];
    __syncthreads();
    for (int j = ty; j < 32; j += 8)
        ohi[(size_t)(n0 + j) * K + k0 + tx] = __float2half_rn(t[tx][j]);
}

// ============================================================
// fp16 tensor-core flash attention. CTA: 64 queries of one (b,h).
// 4 warps x 16 rows; KV tiles of 64; fp32 accum; ctx out fp16.
// ============================================================
__device__ __forceinline__ uint32_t asw(int row, int c8) {   // elem offset, 64-elem rows
    return (uint32_t)(row * 64 + (((c8) ^ (row & 7)) << 3));
}

__global__ __launch_bounds__(128) void attn_mma(const __half* __restrict__ qkv,
    __half* __restrict__ ctx)
{
    __shared__ __half Qs[64 * 64];
    __shared__ __half Ks[64 * 64];
    __shared__ __half Vs[64 * 64];

    const int tid = threadIdx.x, lane = tid & 31, w = tid >> 5;
    const int b = blockIdx.y >> 4, h = blockIdx.y & 15;
    const int t0 = blockIdx.x * 64;
    const __half* base = qkv + (size_t)b * TT * (3 * CD) + h * DKD;

    const uint32_t qsb = smem_to_u32(Qs);
    const uint32_t ksb = smem_to_u32(Ks);
    const uint32_t vsb = smem_to_u32(Vs);

    // load Q: 64 rows over 128 threads (half a row each), prescale by 1/8
    {
        const int row = tid >> 1;
        const __half* src = base + (size_t)(t0 + row) * (3 * CD) + (tid & 1) * 32;
        const __half2 sc = __float2half2_rn(0.125f);
#pragma unroll
        for (int u = 0; u < 4; u++) {
            uint4 d = *(const uint4*)(src + u * 8);
            __half2* p = (__half2*)&d;
#pragma unroll
            for (int q = 0; q < 4; q++) p[q] = __hmul2(p[q], sc);
            *(uint4*)&Qs[asw(row, (tid & 1) * 4 + u)] = d;
        }
    }

    const int arow = (lane & 15);
    const int ac8  = (lane >> 4);
    const int brow = (lane & 7) + ((lane >> 4) & 1) * 8;
    const int bc8  = ((lane >> 3) & 1);
    const int trow = (lane & 7) + ((lane >> 3) & 1) * 8;
    const int tc8  = ((lane >> 4) & 1);
    const int tr = lane >> 2, tc = (lane & 3) * 2;

    float O[8][4];
#pragma unroll
    for (int nt = 0; nt < 8; nt++)
#pragma unroll
        for (int c = 0; c < 4; c++) O[nt][c] = 0.f;
    float m0 = -INFINITY, m1 = -INFINITY, l0 = 0.f, l1 = 0.f;

    for (int kt = 0; kt < TT / 64; kt++) {
        __syncthreads();
        {
            const int row = tid & 63;
            const __half* src = base + (size_t)(kt * 64 + row) * (3 * CD) + ((tid < 64) ? CD : 2 * CD);
            __half* dst = (tid < 64) ? Ks : Vs;
#pragma unroll
            for (int c8 = 0; c8 < 8; c8++)
                *(uint4*)&dst[asw(row, c8)] = *(const uint4*)(src + c8 * 8);
        }
        __syncthreads();

        uint32_t pf[4][4];
        {
            // S = Q @ K^T
            float S[8][4];
#pragma unroll
            for (int nt = 0; nt < 8; nt++)
#pragma unroll
                for (int c = 0; c < 4; c++) S[nt][c] = 0.f;

#pragma unroll
            for (int kb = 0; kb < 4; kb++) {
                uint32_t qf[4];
                ldm_x4(qf, qsb + asw(w * 16 + arow, kb * 2 + ac8) * 2);
                uint32_t kf[4][4];
#pragma unroll
                for (int p = 0; p < 4; p++)
                    ldm_x4(kf[p], ksb + asw(p * 16 + brow, kb * 2 + bc8) * 2);
#pragma unroll
                for (int nt = 0; nt < 8; nt++)
                    mma_f16(S[nt], qf, &kf[nt >> 1][(nt & 1) * 2]);
            }

            // online softmax
            float mx0 = -INFINITY, mx1 = -INFINITY;
#pragma unroll
            for (int nt = 0; nt < 8; nt++) {
                mx0 = fmaxf(mx0, fmaxf(S[nt][0], S[nt][1]));
                mx1 = fmaxf(mx1, fmaxf(S[nt][2], S[nt][3]));
            }
            mx0 = fmaxf(mx0, __shfl_xor_sync(0xffffffffu, mx0, 1, 4));
            mx0 = fmaxf(mx0, __shfl_xor_sync(0xffffffffu, mx0, 2, 4));
            mx1 = fmaxf(mx1, __shfl_xor_sync(0xffffffffu, mx1, 1, 4));
            mx1 = fmaxf(mx1, __shfl_xor_sync(0xffffffffu, mx1, 2, 4));
            float mn0 = fmaxf(m0, mx0);
            float mn1 = fmaxf(m1, mx1);
            float a0 = __expf(m0 - mn0);
            float a1 = __expf(m1 - mn1);
            float ls0 = 0.f, ls1 = 0.f;
#pragma unroll
            for (int nt = 0; nt < 8; nt++) {
                float p0 = __expf(S[nt][0] - mn0);
                float p1 = __expf(S[nt][1] - mn0);
                float p2 = __expf(S[nt][2] - mn1);
                float p3 = __expf(S[nt][3] - mn1);
                ls0 += p0 + p1; ls1 += p2 + p3;
                S[nt][0] = p0; S[nt][1] = p1; S[nt][2] = p2; S[nt][3] = p3;
            }
            ls0 += __shfl_xor_sync(0xffffffffu, ls0, 1, 4);
            ls0 += __shfl_xor_sync(0xffffffffu, ls0, 2, 4);
            ls1 += __shfl_xor_sync(0xffffffffu, ls1, 1, 4);
            ls1 += __shfl_xor_sync(0xffffffffu, ls1, 2, 4);
            l0 = l0 * a0 + ls0;
            l1 = l1 * a1 + ls1;
            m0 = mn0; m1 = mn1;
#pragma unroll
            for (int nt = 0; nt < 8; nt++) {
                O[nt][0] *= a0; O[nt][1] *= a0;
                O[nt][2] *= a1; O[nt][3] *= a1;
            }
#pragma unroll
            for (int g = 0; g < 4; g++) {
                pf[g][0] = packh2(S[2 * g][0], S[2 * g][1]);
                pf[g][1] = packh2(S[2 * g][2], S[2 * g][3]);
                pf[g][2] = packh2(S[2 * g + 1][0], S[2 * g + 1][1]);
                pf[g][3] = packh2(S[2 * g + 1][2], S[2 * g + 1][3]);
            }
        }

        // O += P @ V
#pragma unroll
        for (int kb = 0; kb < 4; kb++) {
            uint32_t vf[4][4];
#pragma unroll
            for (int p = 0; p < 4; p++)
                ldm_x4t(vf[p], vsb + asw(kb * 16 + trow, p * 2 + tc8) * 2);
#pragma unroll
            for (int nt = 0; nt < 8; nt++)
                mma_f16(O[nt], pf[kb], &vf[nt >> 1][(nt & 1) * 2]);
        }
    }

    // epilogue: normalize, store ctx fp16
    float inv0 = 1.f / l0;
    float inv1 = 1.f / l1;
#pragma unroll
    for (int nt = 0; nt < 8; nt++) {
#pragma unroll
        for (int hr = 0; hr < 2; hr++) {
            float inv = hr ? inv1 : inv0;
            float v0 = O[nt][hr * 2 + 0] * inv;
            float v1 = O[nt][hr * 2 + 1] * inv;
            int row = t0 + w * 16 + tr + hr * 8;
            size_t off = (size_t)(b * TT + row) * CD + h * DKD + nt * 8 + tc;
            *(uint32_t*)(ctx + off) = packh2(v0, v1);
        }
    }
}

// ============================================================
// out = LayerNorm(x + res); optional fp16 emission
// ============================================================
__global__ __launch_bounds__(256) void add_ln_kernel(
    const float* __restrict__ x, const float* __restrict__ res,
    const float* __restrict__ gg, const float* __restrict__ bb,
    float* __restrict__ out, __half* __restrict__ oh)
{
    const int row = blockIdx.x, tid = threadIdx.x;
    float4 xv = ((const float4*)(x + (size_t)row * CD))[tid];
    float4 rv = ((const float4*)(res + (size_t)row * CD))[tid];
    float y0 = xv.x + rv.x, y1 = xv.y + rv.y, y2 = xv.z + rv.z, y3 = xv.w + rv.w;
    float s = y0 + y1 + y2 + y3;
    float ss = y0 * y0 + y1 * y1 + y2 * y2 + y3 * y3;
#pragma unroll
    for (int off = 16; off; off >>= 1) {
        s  += __shfl_xor_sync(0xffffffffu, s, off);
        ss += __shfl_xor_sync(0xffffffffu, ss, off);
    }
    __shared__ float rs[8], rss[8];
    if ((tid & 31) == 0) { rs[tid >> 5] = s; rss[tid >> 5] = ss; }
    __syncthreads();
    float tot = 0.f, tots = 0.f;
#pragma unroll
    for (int i = 0; i < 8; i++) { tot += rs[i]; tots += rss[i]; }
    float mean = tot * (1.f / CD);
    float var = tots * (1.f / CD) - mean * mean;
    float iv = rsqrtf(var + 1e-5f);
    float4 gv = ((const float4*)gg)[tid];
    float4 bv = ((const float4*)bb)[tid];
    float w0 = (y0 - mean) * iv * gv.x + bv.x;
    float w1 = (y1 - mean) * iv * gv.y + bv.y;
    float w2 = (y2 - mean) * iv * gv.z + bv.z;
    float w3 = (y3 - mean) * iv * gv.w + bv.w;
    float4 ov = {w0, w1, w2, w3};
    ((float4*)(out + (size_t)row * CD))[tid] = ov;
    if (oh) {
        uint2 o;
        o.x = packh2(w0, w1);
        o.y = packh2(w2, w3);
        *(uint2*)(oh + (size_t)row * CD + tid * 4) = o;
    }
}

// ============================================================
extern "C" void kernel_launch(void* const* d_in, const int* in_sizes, int n_in,
                              void* d_out, int out_size)
{
    const float* x     = (const float*)d_in[0];
    const float* w_qkv = (const float*)d_in[1];
    const float* b_qkv = (const float*)d_in[2];
    const float* w_out = (const float*)d_in[3];
    const float* b_out = (const float*)d_in[4];
    const float* w1    = (const float*)d_in[5];
    const float* b1    = (const float*)d_in[6];
    const float* w2    = (const float*)d_in[7];
    const float* b2    = (const float*)d_in[8];
    const float* ln1g  = (const float*)d_in[9];
    const float* ln1b  = (const float*)d_in[10];
    const float* ln2g  = (const float*)d_in[11];
    const float* ln2b  = (const float*)d_in[12];
    float* out = (float*)d_out;

    float *tmp, *x1;
    __half *qkvh, *ah, *ctxh, *hh, *wth;
    cudaGetSymbolAddress((void**)&qkvh, g_qkvh);
    cudaGetSymbolAddress((void**)&tmp,  g_tmp);
    cudaGetSymbolAddress((void**)&x1,   g_x1);
    cudaGetSymbolAddress((void**)&ah,   g_ah);
    cudaGetSymbolAddress((void**)&ctxh, g_ctxh);
    cudaGetSymbolAddress((void**)&hh,   g_hh);
    cudaGetSymbolAddress((void**)&wth,  g_wth);

    cudaFuncSetAttribute(gemm_mma, cudaFuncAttributeMaxDynamicSharedMemorySize, GSM_BYTES);

    dim3 tblk(32, 8);

    // x -> fp16
    convert_h<<<(BT * CD / 8 + 255) / 256, 256>>>(x, ah, BT * CD / 8);
    // qkv = x @ w_qkv + b_qkv  (out fp16)
    convert_wT<<<dim3(3 * CD / 32, CD / 32), tblk>>>(w_qkv, wth, CD, 3 * CD);
    gemm_mma<<<dim3(3 * CD / 128, BT / 128), 256, GSM_BYTES>>>(
        ah, wth, b_qkv, nullptr, qkvh, 3 * CD, CD, 0);
    // ctx = attention(qkv) -> fp16
    attn_mma<<<dim3(TT / 64, NB * NH), 128>>>(qkvh, ctxh);
    // attn_out = ctx @ w_out + b_out (out fp32)
    convert_wT<<<dim3(CD / 32, CD / 32), tblk>>>(w_out, wth, CD, CD);
    gemm_mma<<<dim3(CD / 128, BT / 128), 256, GSM_BYTES>>>(
        ctxh, wth, b_out, tmp, nullptr, CD, CD, 0);
    // x1 = LN(x + attn_out), emit fp16 into ah
    add_ln_kernel<<<BT, 256>>>(x, tmp, ln1g, ln1b, x1, ah);
    // h = relu(x1 @ w1 + b1) (out fp16)
    convert_wT<<<dim3(FFD / 32, CD / 32), tblk>>>(w1, wth, CD, FFD);
    gemm_mma<<<dim3(FFD / 128, BT / 128), 256, GSM_BYTES>>>(
        ah, wth, b1, nullptr, hh, FFD, CD, 1);
    // ffn_out = h @ w2 + b2 (out fp32)
    convert_wT<<<dim3(CD / 32, FFD / 32), tblk>>>(w2, wth, FFD, CD);
    gemm_mma<<<dim3(CD / 128, BT / 128), 256, GSM_BYTES>>>(
        hh, wth, b2, tmp, nullptr, CD, FFD, 0);
    // out = LN(x1 + ffn_out)
    add_ln_kernel<<<BT, 256>>>(x1, tmp, ln2g, ln2b, out, nullptr);
}

// round 10
// speedup vs baseline: 9.7648x; 1.2180x over previous
#include <cuda_runtime.h>
#include <cuda_fp16.h>
#include <math.h>
#include <stdint.h>

#define NB 4
#define TT 2048
#define BT 8192      // NB*TT
#define CD 1024
#define FFD 4096
#define NH 16
#define DKD 64

// ---------------- scratch (device globals) ----------------
__device__ __half g_qkvh[BT * 3 * CD];   // fp16 qkv
__device__ float  g_tmp [BT * CD];       // fp32 (attn_out / ffn_out)
__device__ float  g_x1  [BT * CD];       // fp32 post-LN1
__device__ __half g_ah  [BT * CD];       // fp16 activation (x, then x1)
__device__ __half g_ctxh[BT * CD];       // fp16 ctx
__device__ __half g_hh  [BT * FFD];      // fp16 FFN hidden
__device__ __half g_wth [FFD * CD];      // fp16 weight, transposed [N,K]

__device__ __forceinline__ uint32_t smem_to_u32(const void* p) {
    uint32_t a;
    asm("{ .reg .u64 t; cvta.to.shared.u64 t, %1; cvt.u32.u64 %0, t; }" : "=r"(a) : "l"(p));
    return a;
}
#define CP_ASYNC16(sm, gp) \
    asm volatile("cp.async.cg.shared.global [%0], [%1], 16;" :: "r"(sm), "l"(gp))
#define CP_COMMIT() asm volatile("cp.async.commit_group;" ::: "memory")
#define CP_WAIT0()  asm volatile("cp.async.wait_group 0;" ::: "memory")
#define CP_WAIT1()  asm volatile("cp.async.wait_group 1;" ::: "memory")

__device__ __forceinline__ void ldm_x4(uint32_t* r, uint32_t addr) {
    asm volatile("ldmatrix.sync.aligned.m8n8.x4.shared.b16 {%0,%1,%2,%3}, [%4];"
        : "=r"(r[0]), "=r"(r[1]), "=r"(r[2]), "=r"(r[3]) : "r"(addr));
}
__device__ __forceinline__ void ldm_x4t(uint32_t* r, uint32_t addr) {
    asm volatile("ldmatrix.sync.aligned.m8n8.x4.trans.shared.b16 {%0,%1,%2,%3}, [%4];"
        : "=r"(r[0]), "=r"(r[1]), "=r"(r[2]), "=r"(r[3]) : "r"(addr));
}
__device__ __forceinline__ void mma_f16(float* c, const uint32_t* a, const uint32_t* b) {
    asm volatile("mma.sync.aligned.m16n8k16.row.col.f32.f16.f16.f32 "
        "{%0,%1,%2,%3}, {%4,%5,%6,%7}, {%8,%9}, {%0,%1,%2,%3};"
        : "+f"(c[0]), "+f"(c[1]), "+f"(c[2]), "+f"(c[3])
        : "r"(a[0]), "r"(a[1]), "r"(a[2]), "r"(a[3]), "r"(b[0]), "r"(b[1]));
}
__device__ __forceinline__ uint32_t packh2(float a, float b) {
    __half2 t = __floats2half2_rn(a, b);
    return *(uint32_t*)&t;
}

// ============================================================
// fp16 GEMM: C[M,N] = A[M,K] @ B^T (B stored [N,K]).
// 128x128 tile, BK=32, 8 warps x (64x32), cp.async double buffer.
// ============================================================
#define BKC 32
#define AST 40                       // halves per smem row (80B) - conflict-free ldmatrix
#define TILE_B2 (128 * AST * 2)      // 10240 B per tile
#define BUFB (2 * TILE_B2)           // A + B
#define GSM_BYTES (2 * BUFB)         // double buffered: 40960

__device__ __forceinline__ void load_chunk(uint32_t sbuf,
    const __half* A, const __half* B, int K, int k0, int tid)
{
#pragma unroll
    for (int j = 0; j < 2; j++) {
        int v = tid + 256 * j;
        int row = v >> 2, c8 = v & 3;
        uint32_t doff = (uint32_t)(row * AST + c8 * 8) * 2;
        size_t goff = (size_t)row * K + k0 + c8 * 8;
        CP_ASYNC16(sbuf + doff, A + goff);
        CP_ASYNC16(sbuf + TILE_B2 + doff, B + goff);
    }
}

__global__ __launch_bounds__(256)
void gemm_mma(const __half* __restrict__ A0, const __half* __restrict__ B0,
              const float* __restrict__ bias,
              float* __restrict__ Cf, __half* __restrict__ Ch,
              int N, int K, int relu)
{
    extern __shared__ char dsm[];
    const uint32_t sb = smem_to_u32(dsm);
    const int tid = threadIdx.x;
    const int lane = tid & 31;
    const int w = tid >> 5;
    const int wm = w & 1, wn = w >> 1;
    const int bm0 = blockIdx.y * 128;
    const int bn0 = blockIdx.x * 128;

    const __half* A = A0 + (size_t)bm0 * K;
    const __half* B = B0 + (size_t)bn0 * K;

    float acc[4][4][4];
#pragma unroll
    for (int a = 0; a < 4; a++)
#pragma unroll
        for (int b = 0; b < 4; b++)
#pragma unroll
            for (int c = 0; c < 4; c++) acc[a][b][c] = 0.f;

    const int arow = (lane & 7) + ((lane >> 3) & 1) * 8;
    const int acol = ((lane >> 4) & 1) * 8;
    const int brow = (lane & 7) + ((lane >> 4) & 1) * 8;
    const int bcol = ((lane >> 3) & 1) * 8;

    const int nch = K / BKC;
    load_chunk(sb, A, B, K, 0, tid);
    CP_COMMIT();

    for (int i = 0; i < nch; i++) {
        if (i + 1 < nch) {
            load_chunk(sb + ((i + 1) & 1) * BUFB, A, B, K, (i + 1) * BKC, tid);
            CP_COMMIT();
            CP_WAIT1();
        } else {
            CP_WAIT0();
        }
        __syncthreads();

        const uint32_t buf = sb + (i & 1) * BUFB;
#pragma unroll
        for (int kk = 0; kk < 2; kk++) {
            const int kb = kk * 16;
            uint32_t af[4][4], bf[2][4];
#pragma unroll
            for (int mt = 0; mt < 4; mt++) {
                int r = wm * 64 + mt * 16 + arow;
                ldm_x4(af[mt], buf + (uint32_t)(r * AST + kb + acol) * 2);
            }
#pragma unroll
            for (int nt2 = 0; nt2 < 2; nt2++) {
                int r = wn * 32 + nt2 * 16 + brow;
                ldm_x4(bf[nt2], buf + TILE_B2 + (uint32_t)(r * AST + kb + bcol) * 2);
            }
#pragma unroll
            for (int mt = 0; mt < 4; mt++)
#pragma unroll
                for (int nt = 0; nt < 4; nt++)
                    mma_f16(acc[mt][nt], af[mt], &bf[nt >> 1][(nt & 1) * 2]);
        }
        __syncthreads();
    }

    const int tr = lane >> 2, tc = (lane & 3) * 2;
    const int r0 = bm0 + wm * 64;
    const int c0 = bn0 + wn * 32;
#pragma unroll
    for (int mt = 0; mt < 4; mt++) {
#pragma unroll
        for (int nt = 0; nt < 4; nt++) {
            const int col = c0 + nt * 8 + tc;
            const float2 bv = *(const float2*)(bias + col);
#pragma unroll
            for (int h = 0; h < 2; h++) {
                const int row = r0 + mt * 16 + tr + h * 8;
                float v0 = acc[mt][nt][h * 2 + 0] + bv.x;
                float v1 = acc[mt][nt][h * 2 + 1] + bv.y;
                if (relu) { v0 = fmaxf(v0, 0.f); v1 = fmaxf(v1, 0.f); }
                if (Cf) {
                    float2 o = {v0, v1};
                    *(float2*)(Cf + (size_t)row * N + col) = o;
                } else {
                    *(uint32_t*)(Ch + (size_t)row * N + col) = packh2(v0, v1);
                }
            }
        }
    }
}

// ============================================================
// conversions
// ============================================================
__global__ __launch_bounds__(256) void convert_h(const float* __restrict__ in,
    __half* __restrict__ oh, int n8)
{
    int i = blockIdx.x * 256 + threadIdx.x;
    if (i >= n8) return;
    float4 a = ((const float4*)in)[2 * i];
    float4 b = ((const float4*)in)[2 * i + 1];
    uint4 o;
    o.x = packh2(a.x, a.y); o.y = packh2(a.z, a.w);
    o.z = packh2(b.x, b.y); o.w = packh2(b.z, b.w);
    ((uint4*)oh)[i] = o;
}

// weight [K,N] fp32 -> [N,K] fp16 (transpose)
__global__ void convert_wT(const float* __restrict__ in,
    __half* __restrict__ ohi, int K, int N)
{
    __shared__ float t[32][33];
    int n0 = blockIdx.x * 32, k0 = blockIdx.y * 32;
    int tx = threadIdx.x, ty = threadIdx.y;
    for (int j = ty; j < 32; j += 8) t[j][tx] = in[(size_t)(k0 + j) * N + n0 + tx];
    __syncthreads();
    for (int j = ty; j < 32; j += 8)
        ohi[(size_t)(n0 + j) * K + k0 + tx] = __float2half_rn(t[tx][j]);
}

// ============================================================
// fp16 tensor-core flash attention. CTA: 128 queries of one (b,h).
// 4 warps x 32 rows; KV tiles of 64, cp.async double-buffered;
// Q fragments hoisted to registers; fp32 accum; ctx out fp16.
// smem: Q 16KB | K0 8KB | V0 8KB | K1 8KB | V1 8KB = 48KB dynamic.
// ============================================================
#define ASM_Q   0
#define ASM_KV  16384
#define ASM_KVB 16384            // per-stage K+V bytes
#define ASM_TOTAL 49152

__device__ __forceinline__ uint32_t asw(int row, int c8) {   // elem offset, 64-elem rows
    return (uint32_t)(row * 64 + (((c8) ^ (row & 7)) << 3));
}

__device__ __forceinline__ void attn_load_kv(uint32_t kvb, const __half* base,
                                             int kt, int tid)
{
#pragma unroll
    for (int j = 0; j < 4; j++) {
        int v = tid + 128 * j;
        int row = v >> 3, c8 = v & 7;
        const __half* src = base + (size_t)(kt * 64 + row) * (3 * CD) + c8 * 8;
        uint32_t dst = kvb + asw(row, c8) * 2;
        CP_ASYNC16(dst, src + CD);              // K
        CP_ASYNC16(dst + 8192, src + 2 * CD);   // V
    }
}

__global__ __launch_bounds__(128) void attn_mma(const __half* __restrict__ qkv,
    __half* __restrict__ ctx)
{
    extern __shared__ char asm_smem[];
    const uint32_t sbase = smem_to_u32(asm_smem);
    const uint32_t qsb = sbase + ASM_Q;

    const int tid = threadIdx.x, lane = tid & 31, w = tid >> 5;
    const int b = blockIdx.y >> 4, h = blockIdx.y & 15;
    const int t0 = blockIdx.x * 128;
    const __half* base = qkv + (size_t)b * TT * (3 * CD) + h * DKD;

    // prefetch KV tile 0 while we set up Q
    attn_load_kv(sbase + ASM_KV, base, 0, tid);
    CP_COMMIT();

    // load Q row `tid`, prescale by 1/8 (exact), swizzle into smem
    {
        const __half* src = base + (size_t)(t0 + tid) * (3 * CD);
        const __half2 sc = __float2half2_rn(0.125f);
#pragma unroll
        for (int c8 = 0; c8 < 8; c8++) {
            uint4 d = *(const uint4*)(src + c8 * 8);
            __half2* p = (__half2*)&d;
#pragma unroll
            for (int u = 0; u < 4; u++) p[u] = __hmul2(p[u], sc);
            *(uint4*)&((__half*)asm_smem)[asw(tid, c8)] = d;
        }
    }
    __syncthreads();

    const int arow = (lane & 15);
    const int ac8  = (lane >> 4);
    const int brow = (lane & 7) + ((lane >> 4) & 1) * 8;
    const int bc8  = ((lane >> 3) & 1);
    const int trow = (lane & 7) + ((lane >> 3) & 1) * 8;
    const int tc8  = ((lane >> 4) & 1);
    const int tr = lane >> 2, tc = (lane & 3) * 2;

    // hoist Q fragments (loop-invariant): 2 mt x 4 kb x 4 regs
    uint32_t qfr[2][4][4];
#pragma unroll
    for (int mt = 0; mt < 2; mt++)
#pragma unroll
        for (int kb = 0; kb < 4; kb++)
            ldm_x4(qfr[mt][kb], qsb + asw(w * 32 + mt * 16 + arow, kb * 2 + ac8) * 2);

    float O[2][8][4];
#pragma unroll
    for (int mt = 0; mt < 2; mt++)
#pragma unroll
        for (int nt = 0; nt < 8; nt++)
#pragma unroll
            for (int c = 0; c < 4; c++) O[mt][nt][c] = 0.f;
    float mrow[2][2], lrow[2][2];
#pragma unroll
    for (int mt = 0; mt < 2; mt++) { mrow[mt][0] = mrow[mt][1] = -INFINITY; lrow[mt][0] = lrow[mt][1] = 0.f; }

    const int NKT = TT / 64;
    for (int kt = 0; kt < NKT; kt++) {
        if (kt + 1 < NKT) {
            attn_load_kv(sbase + ASM_KV + ((kt + 1) & 1) * ASM_KVB, base, kt + 1, tid);
            CP_COMMIT();
            CP_WAIT1();
        } else {
            CP_WAIT0();
        }
        __syncthreads();

        const uint32_t ksb = sbase + ASM_KV + (kt & 1) * ASM_KVB;
        const uint32_t vsb = ksb + 8192;

        // S = Q @ K^T
        float S[2][8][4];
#pragma unroll
        for (int mt = 0; mt < 2; mt++)
#pragma unroll
            for (int nt = 0; nt < 8; nt++)
#pragma unroll
                for (int c = 0; c < 4; c++) S[mt][nt][c] = 0.f;

#pragma unroll
        for (int kb = 0; kb < 4; kb++) {
            uint32_t kf[4][4];
#pragma unroll
            for (int p = 0; p < 4; p++)
                ldm_x4(kf[p], ksb + asw(p * 16 + brow, kb * 2 + bc8) * 2);
#pragma unroll
            for (int mt = 0; mt < 2; mt++)
#pragma unroll
                for (int nt = 0; nt < 8; nt++)
                    mma_f16(S[mt][nt], qfr[mt][kb], &kf[nt >> 1][(nt & 1) * 2]);
        }

        // online softmax + pack P (fp16)
        uint32_t pf[2][4][4];
#pragma unroll
        for (int mt = 0; mt < 2; mt++) {
            float mx0 = -INFINITY, mx1 = -INFINITY;
#pragma unroll
            for (int nt = 0; nt < 8; nt++) {
                mx0 = fmaxf(mx0, fmaxf(S[mt][nt][0], S[mt][nt][1]));
                mx1 = fmaxf(mx1, fmaxf(S[mt][nt][2], S[mt][nt][3]));
            }
            mx0 = fmaxf(mx0, __shfl_xor_sync(0xffffffffu, mx0, 1, 4));
            mx0 = fmaxf(mx0, __shfl_xor_sync(0xffffffffu, mx0, 2, 4));
            mx1 = fmaxf(mx1, __shfl_xor_sync(0xffffffffu, mx1, 1, 4));
            mx1 = fmaxf(mx1, __shfl_xor_sync(0xffffffffu, mx1, 2, 4));
            float mn0 = fmaxf(mrow[mt][0], mx0);
            float mn1 = fmaxf(mrow[mt][1], mx1);
            float a0 = __expf(mrow[mt][0] - mn0);
            float a1 = __expf(mrow[mt][1] - mn1);
            float ls0 = 0.f, ls1 = 0.f;
#pragma unroll
            for (int nt = 0; nt < 8; nt++) {
                float p0 = __expf(S[mt][nt][0] - mn0);
                float p1 = __expf(S[mt][nt][1] - mn0);
                float p2 = __expf(S[mt][nt][2] - mn1);
                float p3 = __expf(S[mt][nt][3] - mn1);
                ls0 += p0 + p1; ls1 += p2 + p3;
                S[mt][nt][0] = p0; S[mt][nt][1] = p1; S[mt][nt][2] = p2; S[mt][nt][3] = p3;
            }
            ls0 += __shfl_xor_sync(0xffffffffu, ls0, 1, 4);
            ls0 += __shfl_xor_sync(0xffffffffu, ls0, 2, 4);
            ls1 += __shfl_xor_sync(0xffffffffu, ls1, 1, 4);
            ls1 += __shfl_xor_sync(0xffffffffu, ls1, 2, 4);
            lrow[mt][0] = lrow[mt][0] * a0 + ls0;
            lrow[mt][1] = lrow[mt][1] * a1 + ls1;
            mrow[mt][0] = mn0; mrow[mt][1] = mn1;
#pragma unroll
            for (int nt = 0; nt < 8; nt++) {
                O[mt][nt][0] *= a0; O[mt][nt][1] *= a0;
                O[mt][nt][2] *= a1; O[mt][nt][3] *= a1;
            }
#pragma unroll
            for (int g = 0; g < 4; g++) {
                pf[mt][g][0] = packh2(S[mt][2 * g][0], S[mt][2 * g][1]);
                pf[mt][g][1] = packh2(S[mt][2 * g][2], S[mt][2 * g][3]);
                pf[mt][g][2] = packh2(S[mt][2 * g + 1][0], S[mt][2 * g + 1][1]);
                pf[mt][g][3] = packh2(S[mt][2 * g + 1][2], S[mt][2 * g + 1][3]);
            }
        }

        // O += P @ V
#pragma unroll
        for (int kb = 0; kb < 4; kb++) {
            uint32_t vf[4][4];
#pragma unroll
            for (int p = 0; p < 4; p++)
                ldm_x4t(vf[p], vsb + asw(kb * 16 + trow, p * 2 + tc8) * 2);
#pragma unroll
            for (int mt = 0; mt < 2; mt++)
#pragma unroll
                for (int nt = 0; nt < 8; nt++)
                    mma_f16(O[mt][nt], pf[mt][kb], &vf[nt >> 1][(nt & 1) * 2]);
        }
        __syncthreads();
    }

    // epilogue: normalize, store ctx fp16
#pragma unroll
    for (int mt = 0; mt < 2; mt++) {
        float inv0 = 1.f / lrow[mt][0];
        float inv1 = 1.f / lrow[mt][1];
#pragma unroll
        for (int nt = 0; nt < 8; nt++) {
#pragma unroll
            for (int hr = 0; hr < 2; hr++) {
                float inv = hr ? inv1 : inv0;
                float v0 = O[mt][nt][hr * 2 + 0] * inv;
                float v1 = O[mt][nt][hr * 2 + 1] * inv;
                int row = t0 + w * 32 + mt * 16 + tr + hr * 8;
                size_t off = (size_t)(b * TT + row) * CD + h * DKD + nt * 8 + tc;
                *(uint32_t*)(ctx + off) = packh2(v0, v1);
            }
        }
    }
}

// ============================================================
// out = LayerNorm(x + res); optional fp16 emission
// ============================================================
__global__ __launch_bounds__(256) void add_ln_kernel(
    const float* __restrict__ x, const float* __restrict__ res,
    const float* __restrict__ gg, const float* __restrict__ bb,
    float* __restrict__ out, __half* __restrict__ oh)
{
    const int row = blockIdx.x, tid = threadIdx.x;
    float4 xv = ((const float4*)(x + (size_t)row * CD))[tid];
    float4 rv = ((const float4*)(res + (size_t)row * CD))[tid];
    float y0 = xv.x + rv.x, y1 = xv.y + rv.y, y2 = xv.z + rv.z, y3 = xv.w + rv.w;
    float s = y0 + y1 + y2 + y3;
    float ss = y0 * y0 + y1 * y1 + y2 * y2 + y3 * y3;
#pragma unroll
    for (int off = 16; off; off >>= 1) {
        s  += __shfl_xor_sync(0xffffffffu, s, off);
        ss += __shfl_xor_sync(0xffffffffu, ss, off);
    }
    __shared__ float rs[8], rss[8];
    if ((tid & 31) == 0) { rs[tid >> 5] = s; rss[tid >> 5] = ss; }
    __syncthreads();
    float tot = 0.f, tots = 0.f;
#pragma unroll
    for (int i = 0; i < 8; i++) { tot += rs[i]; tots += rss[i]; }
    float mean = tot * (1.f / CD);
    float var = tots * (1.f / CD) - mean * mean;
    float iv = rsqrtf(var + 1e-5f);
    float4 gv = ((const float4*)gg)[tid];
    float4 bv = ((const float4*)bb)[tid];
    float w0 = (y0 - mean) * iv * gv.x + bv.x;
    float w1 = (y1 - mean) * iv * gv.y + bv.y;
    float w2 = (y2 - mean) * iv * gv.z + bv.z;
    float w3 = (y3 - mean) * iv * gv.w + bv.w;
    float4 ov = {w0, w1, w2, w3};
    ((float4*)(out + (size_t)row * CD))[tid] = ov;
    if (oh) {
        uint2 o;
        o.x = packh2(w0, w1);
        o.y = packh2(w2, w3);
        *(uint2*)(oh + (size_t)row * CD + tid * 4) = o;
    }
}

// ============================================================
extern "C" void kernel_launch(void* const* d_in, const int* in_sizes, int n_in,
                              void* d_out, int out_size)
{
    const float* x     = (const float*)d_in[0];
    const float* w_qkv = (const float*)d_in[1];
    const float* b_qkv = (const float*)d_in[2];
    const float* w_out = (const float*)d_in[3];
    const float* b_out = (const float*)d_in[4];
    const float* w1    = (const float*)d_in[5];
    const float* b1    = (const float*)d_in[6];
    const float* w2    = (const float*)d_in[7];
    const float* b2    = (const float*)d_in[8];
    const float* ln1g  = (const float*)d_in[9];
    const float* ln1b  = (const float*)d_in[10];
    const float* ln2g  = (const float*)d_in[11];
    const float* ln2b  = (const float*)d_in[12];
    float* out = (float*)d_out;

    float *tmp, *x1;
    __half *qkvh, *ah, *ctxh, *hh, *wth;
    cudaGetSymbolAddress((void**)&qkvh, g_qkvh);
    cudaGetSymbolAddress((void**)&tmp,  g_tmp);
    cudaGetSymbolAddress((void**)&x1,   g_x1);
    cudaGetSymbolAddress((void**)&ah,   g_ah);
    cudaGetSymbolAddress((void**)&ctxh, g_ctxh);
    cudaGetSymbolAddress((void**)&hh,   g_hh);
    cudaGetSymbolAddress((void**)&wth,  g_wth);

    cudaFuncSetAttribute(gemm_mma, cudaFuncAttributeMaxDynamicSharedMemorySize, GSM_BYTES);
    cudaFuncSetAttribute(attn_mma, cudaFuncAttributeMaxDynamicSharedMemorySize, ASM_TOTAL);

    dim3 tblk(32, 8);

    // x -> fp16
    convert_h<<<(BT * CD / 8 + 255) / 256, 256>>>(x, ah, BT * CD / 8);
    // qkv = x @ w_qkv + b_qkv  (out fp16)
    convert_wT<<<dim3(3 * CD / 32, CD / 32), tblk>>>(w_qkv, wth, CD, 3 * CD);
    gemm_mma<<<dim3(3 * CD / 128, BT / 128), 256, GSM_BYTES>>>(
        ah, wth, b_qkv, nullptr, qkvh, 3 * CD, CD, 0);
    // ctx = attention(qkv) -> fp16
    attn_mma<<<dim3(TT / 128, NB * NH), 128, ASM_TOTAL>>>(qkvh, ctxh);
    // attn_out = ctx @ w_out + b_out (out fp32)
    convert_wT<<<dim3(CD / 32, CD / 32), tblk>>>(w_out, wth, CD, CD);
    gemm_mma<<<dim3(CD / 128, BT / 128), 256, GSM_BYTES>>>(
        ctxh, wth, b_out, tmp, nullptr, CD, CD, 0);
    // x1 = LN(x + attn_out), emit fp16 into ah
    add_ln_kernel<<<BT, 256>>>(x, tmp, ln1g, ln1b, x1, ah);
    // h = relu(x1 @ w1 + b1) (out fp16)
    convert_wT<<<dim3(FFD / 32, CD / 32), tblk>>>(w1, wth, CD, FFD);
    gemm_mma<<<dim3(FFD / 128, BT / 128), 256, GSM_BYTES>>>(
        ah, wth, b1, nullptr, hh, FFD, CD, 1);
    // ffn_out = h @ w2 + b2 (out fp32)
    convert_wT<<<dim3(CD / 32, FFD / 32), tblk>>>(w2, wth, FFD, CD);
    gemm_mma<<<dim3(CD / 128, BT / 128), 256, GSM_BYTES>>>(
        hh, wth, b2, tmp, nullptr, CD, FFD, 0);
    // out = LN(x1 + ffn_out)
    add_ln_kernel<<<BT, 256>>>(x1, tmp, ln2g, ln2b, out, nullptr);
}

// round 11
// speedup vs baseline: 11.4663x; 1.1742x over previous
#include <cuda_runtime.h>
#include <cuda_fp16.h>
#include <math.h>
#include <stdint.h>

#define NB 4
#define TT 2048
#define BT 8192      // NB*TT
#define CD 1024
#define FFD 4096
#define NH 16
#define DKD 64

// ---------------- scratch (device globals) ----------------
__device__ __half g_qkvh[BT * 3 * CD];   // fp16 qkv
__device__ float  g_tmp [BT * CD];       // fp32 (attn_out / ffn_out)
__device__ float  g_x1  [BT * CD];       // fp32 post-LN1
__device__ __half g_ah  [BT * CD];       // fp16 activation (x, then x1)
__device__ __half g_ctxh[BT * CD];       // fp16 ctx
__device__ __half g_hh  [BT * FFD];      // fp16 FFN hidden
__device__ __half g_wth [FFD * CD];      // fp16 weight, transposed [N,K]

__device__ __forceinline__ uint32_t smem_to_u32(const void* p) {
    uint32_t a;
    asm("{ .reg .u64 t; cvta.to.shared.u64 t, %1; cvt.u32.u64 %0, t; }" : "=r"(a) : "l"(p));
    return a;
}
#define CP_ASYNC16(sm, gp) \
    asm volatile("cp.async.cg.shared.global [%0], [%1], 16;" :: "r"(sm), "l"(gp))
#define CP_COMMIT() asm volatile("cp.async.commit_group;" ::: "memory")
#define CP_WAIT0()  asm volatile("cp.async.wait_group 0;" ::: "memory")
#define CP_WAIT1()  asm volatile("cp.async.wait_group 1;" ::: "memory")

__device__ __forceinline__ void ldm_x4(uint32_t* r, uint32_t addr) {
    asm volatile("ldmatrix.sync.aligned.m8n8.x4.shared.b16 {%0,%1,%2,%3}, [%4];"
        : "=r"(r[0]), "=r"(r[1]), "=r"(r[2]), "=r"(r[3]) : "r"(addr));
}
__device__ __forceinline__ void ldm_x4t(uint32_t* r, uint32_t addr) {
    asm volatile("ldmatrix.sync.aligned.m8n8.x4.trans.shared.b16 {%0,%1,%2,%3}, [%4];"
        : "=r"(r[0]), "=r"(r[1]), "=r"(r[2]), "=r"(r[3]) : "r"(addr));
}
__device__ __forceinline__ void mma_f16(float* c, const uint32_t* a, const uint32_t* b) {
    asm volatile("mma.sync.aligned.m16n8k16.row.col.f32.f16.f16.f32 "
        "{%0,%1,%2,%3}, {%4,%5,%6,%7}, {%8,%9}, {%0,%1,%2,%3};"
        : "+f"(c[0]), "+f"(c[1]), "+f"(c[2]), "+f"(c[3])
        : "r"(a[0]), "r"(a[1]), "r"(a[2]), "r"(a[3]), "r"(b[0]), "r"(b[1]));
}
__device__ __forceinline__ uint32_t packh2(float a, float b) {
    __half2 t = __floats2half2_rn(a, b);
    return *(uint32_t*)&t;
}
__device__ __forceinline__ uint32_t ex2h2(float a, float b) {
    __half2 t = __floats2half2_rn(a, b);
    uint32_t y = *(uint32_t*)&t, o;
    asm volatile("ex2.approx.f16x2 %0, %1;" : "=r"(o) : "r"(y));
    return o;
}

// ============================================================
// fp16 GEMM: C[M,N] = A[M,K] @ B^T (B stored [N,K]).
// 128x128 tile, BK=64, 8 warps x (64x32), cp.async double buffer.
// ============================================================
#define BKC 64
#define AST 72                       // halves per smem row (144B) - conflict-free ldmatrix
#define TILE_B2 (128 * AST * 2)      // 18432 B per tile
#define BUFB (2 * TILE_B2)           // A + B
#define GSM_BYTES (2 * BUFB)         // double buffered: 73728

__device__ __forceinline__ void load_chunk(uint32_t sbuf,
    const __half* A, const __half* B, int K, int k0, int tid)
{
#pragma unroll
    for (int j = 0; j < 4; j++) {
        int v = tid + 256 * j;
        int row = v >> 3, c8 = v & 7;
        uint32_t doff = (uint32_t)(row * AST + c8 * 8) * 2;
        size_t goff = (size_t)row * K + k0 + c8 * 8;
        CP_ASYNC16(sbuf + doff, A + goff);
        CP_ASYNC16(sbuf + TILE_B2 + doff, B + goff);
    }
}

__global__ __launch_bounds__(256)
void gemm_mma(const __half* __restrict__ A0, const __half* __restrict__ B0,
              const float* __restrict__ bias,
              float* __restrict__ Cf, __half* __restrict__ Ch,
              int N, int K, int relu)
{
    extern __shared__ char dsm[];
    const uint32_t sb = smem_to_u32(dsm);
    const int tid = threadIdx.x;
    const int lane = tid & 31;
    const int w = tid >> 5;
    const int wm = w & 1, wn = w >> 1;
    const int bm0 = blockIdx.y * 128;
    const int bn0 = blockIdx.x * 128;

    const __half* A = A0 + (size_t)bm0 * K;
    const __half* B = B0 + (size_t)bn0 * K;

    float acc[4][4][4];
#pragma unroll
    for (int a = 0; a < 4; a++)
#pragma unroll
        for (int b = 0; b < 4; b++)
#pragma unroll
            for (int c = 0; c < 4; c++) acc[a][b][c] = 0.f;

    const int arow = (lane & 7) + ((lane >> 3) & 1) * 8;
    const int acol = ((lane >> 4) & 1) * 8;
    const int brow = (lane & 7) + ((lane >> 4) & 1) * 8;
    const int bcol = ((lane >> 3) & 1) * 8;

    const int nch = K / BKC;
    load_chunk(sb, A, B, K, 0, tid);
    CP_COMMIT();

    for (int i = 0; i < nch; i++) {
        if (i + 1 < nch) {
            load_chunk(sb + ((i + 1) & 1) * BUFB, A, B, K, (i + 1) * BKC, tid);
            CP_COMMIT();
            CP_WAIT1();
        } else {
            CP_WAIT0();
        }
        __syncthreads();

        const uint32_t buf = sb + (i & 1) * BUFB;
#pragma unroll
        for (int kk = 0; kk < 4; kk++) {
            const int kb = kk * 16;
            uint32_t af[4][4], bf[2][4];
#pragma unroll
            for (int mt = 0; mt < 4; mt++) {
                int r = wm * 64 + mt * 16 + arow;
                ldm_x4(af[mt], buf + (uint32_t)(r * AST + kb + acol) * 2);
            }
#pragma unroll
            for (int nt2 = 0; nt2 < 2; nt2++) {
                int r = wn * 32 + nt2 * 16 + brow;
                ldm_x4(bf[nt2], buf + TILE_B2 + (uint32_t)(r * AST + kb + bcol) * 2);
            }
#pragma unroll
            for (int mt = 0; mt < 4; mt++)
#pragma unroll
                for (int nt = 0; nt < 4; nt++)
                    mma_f16(acc[mt][nt], af[mt], &bf[nt >> 1][(nt & 1) * 2]);
        }
        __syncthreads();
    }

    const int tr = lane >> 2, tc = (lane & 3) * 2;
    const int r0 = bm0 + wm * 64;
    const int c0 = bn0 + wn * 32;
#pragma unroll
    for (int mt = 0; mt < 4; mt++) {
#pragma unroll
        for (int nt = 0; nt < 4; nt++) {
            const int col = c0 + nt * 8 + tc;
            const float2 bv = *(const float2*)(bias + col);
#pragma unroll
            for (int h = 0; h < 2; h++) {
                const int row = r0 + mt * 16 + tr + h * 8;
                float v0 = acc[mt][nt][h * 2 + 0] + bv.x;
                float v1 = acc[mt][nt][h * 2 + 1] + bv.y;
                if (relu) { v0 = fmaxf(v0, 0.f); v1 = fmaxf(v1, 0.f); }
                if (Cf) {
                    float2 o = {v0, v1};
                    *(float2*)(Cf + (size_t)row * N + col) = o;
                } else {
                    *(uint32_t*)(Ch + (size_t)row * N + col) = packh2(v0, v1);
                }
            }
        }
    }
}

// ============================================================
// conversions
// ============================================================
__global__ __launch_bounds__(256) void convert_h(const float* __restrict__ in,
    __half* __restrict__ oh, int n8)
{
    int i = blockIdx.x * 256 + threadIdx.x;
    if (i >= n8) return;
    float4 a = ((const float4*)in)[2 * i];
    float4 b = ((const float4*)in)[2 * i + 1];
    uint4 o;
    o.x = packh2(a.x, a.y); o.y = packh2(a.z, a.w);
    o.z = packh2(b.x, b.y); o.w = packh2(b.z, b.w);
    ((uint4*)oh)[i] = o;
}

// weight [K,N] fp32 -> [N,K] fp16 (transpose)
__global__ void convert_wT(const float* __restrict__ in,
    __half* __restrict__ ohi, int K, int N)
{
    __shared__ float t[32][33];
    int n0 = blockIdx.x * 32, k0 = blockIdx.y * 32;
    int tx = threadIdx.x, ty = threadIdx.y;
    for (int j = ty; j < 32; j += 8) t[j][tx] = in[(size_t)(k0 + j) * N + n0 + tx];
    __syncthreads();
    for (int j = ty; j < 32; j += 8)
        ohi[(size_t)(n0 + j) * K + k0 + tx] = __float2half_rn(t[tx][j]);
}

// ============================================================
// fp16 tensor-core flash attention. CTA: 128 queries of one (b,h).
// 4 warps x 32 rows; KV tiles of 64, cp.async double-buffered.
// Q pre-scaled by log2(e)/8 -> logits in log2 domain; P = ex2.f16x2.
// Row-sum l computed by the tensor core via a ones-column fragment.
// smem: Q 16KB | K0 8KB | V0 8KB | K1 8KB | V1 8KB = 48KB dynamic.
// ============================================================
#define ASM_Q   0
#define ASM_KV  16384
#define ASM_KVB 16384            // per-stage K+V bytes
#define ASM_TOTAL 49152

__device__ __forceinline__ uint32_t asw(int row, int c8) {   // elem offset, 64-elem rows
    return (uint32_t)(row * 64 + (((c8) ^ (row & 7)) << 3));
}

__device__ __forceinline__ void attn_load_kv(uint32_t kvb, const __half* base,
                                             int kt, int tid)
{
#pragma unroll
    for (int j = 0; j < 4; j++) {
        int v = tid + 128 * j;
        int row = v >> 3, c8 = v & 7;
        const __half* src = base + (size_t)(kt * 64 + row) * (3 * CD) + c8 * 8;
        uint32_t dst = kvb + asw(row, c8) * 2;
        CP_ASYNC16(dst, src + CD);              // K
        CP_ASYNC16(dst + 8192, src + 2 * CD);   // V
    }
}

__global__ __launch_bounds__(128) void attn_mma(const __half* __restrict__ qkv,
    __half* __restrict__ ctx)
{
    extern __shared__ char asm_smem[];
    const uint32_t sbase = smem_to_u32(asm_smem);
    const uint32_t qsb = sbase + ASM_Q;

    const int tid = threadIdx.x, lane = tid & 31, w = tid >> 5;
    const int b = blockIdx.y >> 4, h = blockIdx.y & 15;
    const int t0 = blockIdx.x * 128;
    const __half* base = qkv + (size_t)b * TT * (3 * CD) + h * DKD;

    // prefetch KV tile 0 while we set up Q
    attn_load_kv(sbase + ASM_KV, base, 0, tid);
    CP_COMMIT();

    // load Q row `tid`, prescale by log2(e)/8 in fp32, swizzle into smem
    {
        const __half* src = base + (size_t)(t0 + tid) * (3 * CD);
        const float qs = 0.1803368801f;   // log2(e) / 8
#pragma unroll
        for (int c8 = 0; c8 < 8; c8++) {
            uint4 d = *(const uint4*)(src + c8 * 8);
            __half2* p = (__half2*)&d;
#pragma unroll
            for (int u = 0; u < 4; u++) {
                float2 f = __half22float2(p[u]);
                p[u] = __floats2half2_rn(f.x * qs, f.y * qs);
            }
            *(uint4*)&((__half*)asm_smem)[asw(tid, c8)] = d;
        }
    }
    __syncthreads();

    const int arow = (lane & 15);
    const int ac8  = (lane >> 4);
    const int brow = (lane & 7) + ((lane >> 4) & 1) * 8;
    const int bc8  = ((lane >> 3) & 1);
    const int trow = (lane & 7) + ((lane >> 3) & 1) * 8;
    const int tc8  = ((lane >> 4) & 1);
    const int tr = lane >> 2, tc = (lane & 3) * 2;

    // ones-column B fragment (V_extra[k][0]=1): lanes 0-3 hold col 0
    uint32_t onesb[2];
    onesb[0] = onesb[1] = (lane < 4) ? 0x3C003C00u : 0u;

    // hoist Q fragments (loop-invariant): 2 mt x 4 kb x 4 regs
    uint32_t qfr[2][4][4];
#pragma unroll
    for (int mt = 0; mt < 2; mt++)
#pragma unroll
        for (int kb = 0; kb < 4; kb++)
            ldm_x4(qfr[mt][kb], qsb + asw(w * 32 + mt * 16 + arow, kb * 2 + ac8) * 2);

    float O[2][8][4];
#pragma unroll
    for (int mt = 0; mt < 2; mt++)
#pragma unroll
        for (int nt = 0; nt < 8; nt++)
#pragma unroll
            for (int c = 0; c < 4; c++) O[mt][nt][c] = 0.f;
    float Oe[2][4];                      // ones-column accumulator (l in col 0)
#pragma unroll
    for (int mt = 0; mt < 2; mt++)
#pragma unroll
        for (int c = 0; c < 4; c++) Oe[mt][c] = 0.f;
    float mrow[2][2];
#pragma unroll
    for (int mt = 0; mt < 2; mt++) { mrow[mt][0] = mrow[mt][1] = -INFINITY; }

    const int NKT = TT / 64;
    for (int kt = 0; kt < NKT; kt++) {
        if (kt + 1 < NKT) {
            attn_load_kv(sbase + ASM_KV + ((kt + 1) & 1) * ASM_KVB, base, kt + 1, tid);
            CP_COMMIT();
            CP_WAIT1();
        } else {
            CP_WAIT0();
        }
        __syncthreads();

        const uint32_t ksb = sbase + ASM_KV + (kt & 1) * ASM_KVB;
        const uint32_t vsb = ksb + 8192;

        // S = Q @ K^T   (S already in log2 domain)
        float S[2][8][4];
#pragma unroll
        for (int mt = 0; mt < 2; mt++)
#pragma unroll
            for (int nt = 0; nt < 8; nt++)
#pragma unroll
                for (int c = 0; c < 4; c++) S[mt][nt][c] = 0.f;

#pragma unroll
        for (int kb = 0; kb < 4; kb++) {
            uint32_t kf[4][4];
#pragma unroll
            for (int p = 0; p < 4; p++)
                ldm_x4(kf[p], ksb + asw(p * 16 + brow, kb * 2 + bc8) * 2);
#pragma unroll
            for (int mt = 0; mt < 2; mt++)
#pragma unroll
                for (int nt = 0; nt < 8; nt++)
                    mma_f16(S[mt][nt], qfr[mt][kb], &kf[nt >> 1][(nt & 1) * 2]);
        }

        // online softmax: P = 2^(S - m), packed fp16 via ex2.approx.f16x2
        uint32_t pf[2][4][4];
#pragma unroll
        for (int mt = 0; mt < 2; mt++) {
            float mx0 = -INFINITY, mx1 = -INFINITY;
#pragma unroll
            for (int nt = 0; nt < 8; nt++) {
                mx0 = fmaxf(mx0, fmaxf(S[mt][nt][0], S[mt][nt][1]));
                mx1 = fmaxf(mx1, fmaxf(S[mt][nt][2], S[mt][nt][3]));
            }
            mx0 = fmaxf(mx0, __shfl_xor_sync(0xffffffffu, mx0, 1, 4));
            mx0 = fmaxf(mx0, __shfl_xor_sync(0xffffffffu, mx0, 2, 4));
            mx1 = fmaxf(mx1, __shfl_xor_sync(0xffffffffu, mx1, 1, 4));
            mx1 = fmaxf(mx1, __shfl_xor_sync(0xffffffffu, mx1, 2, 4));
            float mn0 = fmaxf(mrow[mt][0], mx0);
            float mn1 = fmaxf(mrow[mt][1], mx1);
            float a0 = exp2f(mrow[mt][0] - mn0);
            float a1 = exp2f(mrow[mt][1] - mn1);
            mrow[mt][0] = mn0; mrow[mt][1] = mn1;
#pragma unroll
            for (int g = 0; g < 4; g++) {
                pf[mt][g][0] = ex2h2(S[mt][2 * g][0] - mn0, S[mt][2 * g][1] - mn0);
                pf[mt][g][1] = ex2h2(S[mt][2 * g][2] - mn1, S[mt][2 * g][3] - mn1);
                pf[mt][g][2] = ex2h2(S[mt][2 * g + 1][0] - mn0, S[mt][2 * g + 1][1] - mn0);
                pf[mt][g][3] = ex2h2(S[mt][2 * g + 1][2] - mn1, S[mt][2 * g + 1][3] - mn1);
            }
#pragma unroll
            for (int nt = 0; nt < 8; nt++) {
                O[mt][nt][0] *= a0; O[mt][nt][1] *= a0;
                O[mt][nt][2] *= a1; O[mt][nt][3] *= a1;
            }
            Oe[mt][0] *= a0; Oe[mt][1] *= a0;
            Oe[mt][2] *= a1; Oe[mt][3] *= a1;
        }

        // O += P @ V ; Oe += P @ ones (row sum -> l)
#pragma unroll
        for (int kb = 0; kb < 4; kb++) {
            uint32_t vf[4][4];
#pragma unroll
            for (int p = 0; p < 4; p++)
                ldm_x4t(vf[p], vsb + asw(kb * 16 + trow, p * 2 + tc8) * 2);
#pragma unroll
            for (int mt = 0; mt < 2; mt++) {
#pragma unroll
                for (int nt = 0; nt < 8; nt++)
                    mma_f16(O[mt][nt], pf[mt][kb], &vf[nt >> 1][(nt & 1) * 2]);
                mma_f16(Oe[mt], pf[mt][kb], onesb);
            }
        }
        __syncthreads();
    }

    // epilogue: broadcast l from ones column, normalize, store ctx fp16
#pragma unroll
    for (int mt = 0; mt < 2; mt++) {
        float l0 = __shfl_sync(0xffffffffu, Oe[mt][0], lane & ~3);
        float l1 = __shfl_sync(0xffffffffu, Oe[mt][2], lane & ~3);
        float inv0 = 1.f / l0;
        float inv1 = 1.f / l1;
#pragma unroll
        for (int nt = 0; nt < 8; nt++) {
#pragma unroll
            for (int hr = 0; hr < 2; hr++) {
                float inv = hr ? inv1 : inv0;
                float v0 = O[mt][nt][hr * 2 + 0] * inv;
                float v1 = O[mt][nt][hr * 2 + 1] * inv;
                int row = t0 + w * 32 + mt * 16 + tr + hr * 8;
                size_t off = (size_t)(b * TT + row) * CD + h * DKD + nt * 8 + tc;
                *(uint32_t*)(ctx + off) = packh2(v0, v1);
            }
        }
    }
}

// ============================================================
// out = LayerNorm(x + res); optional fp16 emission
// ============================================================
__global__ __launch_bounds__(256) void add_ln_kernel(
    const float* __restrict__ x, const float* __restrict__ res,
    const float* __restrict__ gg, const float* __restrict__ bb,
    float* __restrict__ out, __half* __restrict__ oh)
{
    const int row = blockIdx.x, tid = threadIdx.x;
    float4 xv = ((const float4*)(x + (size_t)row * CD))[tid];
    float4 rv = ((const float4*)(res + (size_t)row * CD))[tid];
    float y0 = xv.x + rv.x, y1 = xv.y + rv.y, y2 = xv.z + rv.z, y3 = xv.w + rv.w;
    float s = y0 + y1 + y2 + y3;
    float ss = y0 * y0 + y1 * y1 + y2 * y2 + y3 * y3;
#pragma unroll
    for (int off = 16; off; off >>= 1) {
        s  += __shfl_xor_sync(0xffffffffu, s, off);
        ss += __shfl_xor_sync(0xffffffffu, ss, off);
    }
    __shared__ float rs[8], rss[8];
    if ((tid & 31) == 0) { rs[tid >> 5] = s; rss[tid >> 5] = ss; }
    __syncthreads();
    float tot = 0.f, tots = 0.f;
#pragma unroll
    for (int i = 0; i < 8; i++) { tot += rs[i]; tots += rss[i]; }
    float mean = tot * (1.f / CD);
    float var = tots * (1.f / CD) - mean * mean;
    float iv = rsqrtf(var + 1e-5f);
    float4 gv = ((const float4*)gg)[tid];
    float4 bv = ((const float4*)bb)[tid];
    float w0 = (y0 - mean) * iv * gv.x + bv.x;
    float w1 = (y1 - mean) * iv * gv.y + bv.y;
    float w2 = (y2 - mean) * iv * gv.z + bv.z;
    float w3 = (y3 - mean) * iv * gv.w + bv.w;
    float4 ov = {w0, w1, w2, w3};
    ((float4*)(out + (size_t)row * CD))[tid] = ov;
    if (oh) {
        uint2 o;
        o.x = packh2(w0, w1);
        o.y = packh2(w2, w3);
        *(uint2*)(oh + (size_t)row * CD + tid * 4) = o;
    }
}

// ============================================================
extern "C" void kernel_launch(void* const* d_in, const int* in_sizes, int n_in,
                              void* d_out, int out_size)
{
    const float* x     = (const float*)d_in[0];
    const float* w_qkv = (const float*)d_in[1];
    const float* b_qkv = (const float*)d_in[2];
    const float* w_out = (const float*)d_in[3];
    const float* b_out = (const float*)d_in[4];
    const float* w1    = (const float*)d_in[5];
    const float* b1    = (const float*)d_in[6];
    const float* w2    = (const float*)d_in[7];
    const float* b2    = (const float*)d_in[8];
    const float* ln1g  = (const float*)d_in[9];
    const float* ln1b  = (const float*)d_in[10];
    const float* ln2g  = (const float*)d_in[11];
    const float* ln2b  = (const float*)d_in[12];
    float* out = (float*)d_out;

    float *tmp, *x1;
    __half *qkvh, *ah, *ctxh, *hh, *wth;
    cudaGetSymbolAddress((void**)&qkvh, g_qkvh);
    cudaGetSymbolAddress((void**)&tmp,  g_tmp);
    cudaGetSymbolAddress((void**)&x1,   g_x1);
    cudaGetSymbolAddress((void**)&ah,   g_ah);
    cudaGetSymbolAddress((void**)&ctxh, g_ctxh);
    cudaGetSymbolAddress((void**)&hh,   g_hh);
    cudaGetSymbolAddress((void**)&wth,  g_wth);

    cudaFuncSetAttribute(gemm_mma, cudaFuncAttributeMaxDynamicSharedMemorySize, GSM_BYTES);
    cudaFuncSetAttribute(attn_mma, cudaFuncAttributeMaxDynamicSharedMemorySize, ASM_TOTAL);

    dim3 tblk(32, 8);

    // x -> fp16
    convert_h<<<(BT * CD / 8 + 255) / 256, 256>>>(x, ah, BT * CD / 8);
    // qkv = x @ w_qkv + b_qkv  (out fp16)
    convert_wT<<<dim3(3 * CD / 32, CD / 32), tblk>>>(w_qkv, wth, CD, 3 * CD);
    gemm_mma<<<dim3(3 * CD / 128, BT / 128), 256, GSM_BYTES>>>(
        ah, wth, b_qkv, nullptr, qkvh, 3 * CD, CD, 0);
    // ctx = attention(qkv) -> fp16
    attn_mma<<<dim3(TT / 128, NB * NH), 128, ASM_TOTAL>>>(qkvh, ctxh);
    // attn_out = ctx @ w_out + b_out (out fp32)
    convert_wT<<<dim3(CD / 32, CD / 32), tblk>>>(w_out, wth, CD, CD);
    gemm_mma<<<dim3(CD / 128, BT / 128), 256, GSM_BYTES>>>(
        ctxh, wth, b_out, tmp, nullptr, CD, CD, 0);
    // x1 = LN(x + attn_out), emit fp16 into ah
    add_ln_kernel<<<BT, 256>>>(x, tmp, ln1g, ln1b, x1, ah);
    // h = relu(x1 @ w1 + b1) (out fp16)
    convert_wT<<<dim3(FFD / 32, CD / 32), tblk>>>(w1, wth, CD, FFD);
    gemm_mma<<<dim3(FFD / 128, BT / 128), 256, GSM_BYTES>>>(
        ah, wth, b1, nullptr, hh, FFD, CD, 1);
    // ffn_out = h @ w2 + b2 (out fp32)
    convert_wT<<<dim3(CD / 32, FFD / 32), tblk>>>(w2, wth, FFD, CD);
    gemm_mma<<<dim3(CD / 128, BT / 128), 256, GSM_BYTES>>>(
        hh, wth, b2, tmp, nullptr, CD, FFD, 0);
    // out = LN(x1 + ffn_out)
    add_ln_kernel<<<BT, 256>>>(x1, tmp, ln2g, ln2b, out, nullptr);
}

// round 12
// speedup vs baseline: 11.9903x; 1.0457x over previous
#include <cuda_runtime.h>
#include <cuda_fp16.h>
#include <math.h>
#include <stdint.h>

#define NB 4
#define TT 2048
#define BT 8192      // NB*TT
#define CD 1024
#define FFD 4096
#define NH 16
#define DKD 64

// ---------------- scratch (device globals) ----------------
__device__ __half g_qkvh[BT * 3 * CD];   // fp16 qkv
__device__ float  g_tmp [BT * CD];       // fp32 (attn_out / ffn_out)
__device__ float  g_x1  [BT * CD];       // fp32 post-LN1
__device__ __half g_ah  [BT * CD];       // fp16 activation (x, then x1)
__device__ __half g_ctxh[BT * CD];       // fp16 ctx
__device__ __half g_hh  [BT * FFD];      // fp16 FFN hidden
__device__ __half g_wth [FFD * CD];      // fp16 weight, transposed [N,K]

__device__ __forceinline__ uint32_t smem_to_u32(const void* p) {
    uint32_t a;
    asm("{ .reg .u64 t; cvta.to.shared.u64 t, %1; cvt.u32.u64 %0, t; }" : "=r"(a) : "l"(p));
    return a;
}
#define CP_ASYNC16(sm, gp) \
    asm volatile("cp.async.cg.shared.global [%0], [%1], 16;" :: "r"(sm), "l"(gp))
#define CP_COMMIT() asm volatile("cp.async.commit_group;" ::: "memory")
#define CP_WAIT0()  asm volatile("cp.async.wait_group 0;" ::: "memory")
#define CP_WAIT1()  asm volatile("cp.async.wait_group 1;" ::: "memory")

__device__ __forceinline__ void ldm_x4(uint32_t* r, uint32_t addr) {
    asm volatile("ldmatrix.sync.aligned.m8n8.x4.shared.b16 {%0,%1,%2,%3}, [%4];"
        : "=r"(r[0]), "=r"(r[1]), "=r"(r[2]), "=r"(r[3]) : "r"(addr));
}
__device__ __forceinline__ void ldm_x4t(uint32_t* r, uint32_t addr) {
    asm volatile("ldmatrix.sync.aligned.m8n8.x4.trans.shared.b16 {%0,%1,%2,%3}, [%4];"
        : "=r"(r[0]), "=r"(r[1]), "=r"(r[2]), "=r"(r[3]) : "r"(addr));
}
__device__ __forceinline__ void mma_f16(float* c, const uint32_t* a, const uint32_t* b) {
    asm volatile("mma.sync.aligned.m16n8k16.row.col.f32.f16.f16.f32 "
        "{%0,%1,%2,%3}, {%4,%5,%6,%7}, {%8,%9}, {%0,%1,%2,%3};"
        : "+f"(c[0]), "+f"(c[1]), "+f"(c[2]), "+f"(c[3])
        : "r"(a[0]), "r"(a[1]), "r"(a[2]), "r"(a[3]), "r"(b[0]), "r"(b[1]));
}
__device__ __forceinline__ uint32_t packh2(float a, float b) {
    __half2 t = __floats2half2_rn(a, b);
    return *(uint32_t*)&t;
}
__device__ __forceinline__ uint32_t ex2h2(float a, float b) {
    __half2 t = __floats2half2_rn(a, b);
    uint32_t y = *(uint32_t*)&t, o;
    asm volatile("ex2.approx.f16x2 %0, %1;" : "=r"(o) : "r"(y));
    return o;
}

// ============================================================
// fp16 GEMM: C[M,N] = A[M,K] @ B^T (B stored [N,K]).
// 128x128 tile, BK=64, 8 warps x (64x32), 3-stage cp.async pipeline,
// single __syncthreads per K-chunk.
// ============================================================
#define BKC 64
#define AST 72                       // halves per smem row (144B) - conflict-free ldmatrix
#define TILE_B2 (128 * AST * 2)      // 18432 B per tile
#define BUFB (2 * TILE_B2)           // A + B per stage
#define GSM_BYTES (3 * BUFB)         // 3 stages: 110592

__device__ __forceinline__ void load_chunk(uint32_t sbuf,
    const __half* A, const __half* B, int K, int k0, int tid)
{
#pragma unroll
    for (int j = 0; j < 4; j++) {
        int v = tid + 256 * j;
        int row = v >> 3, c8 = v & 7;
        uint32_t doff = (uint32_t)(row * AST + c8 * 8) * 2;
        size_t goff = (size_t)row * K + k0 + c8 * 8;
        CP_ASYNC16(sbuf + doff, A + goff);
        CP_ASYNC16(sbuf + TILE_B2 + doff, B + goff);
    }
}

__global__ __launch_bounds__(256)
void gemm_mma(const __half* __restrict__ A0, const __half* __restrict__ B0,
              const float* __restrict__ bias,
              float* __restrict__ Cf, __half* __restrict__ Ch,
              int N, int K, int relu)
{
    extern __shared__ char dsm[];
    const uint32_t sb = smem_to_u32(dsm);
    const int tid = threadIdx.x;
    const int lane = tid & 31;
    const int w = tid >> 5;
    const int wm = w & 1, wn = w >> 1;
    const int bm0 = blockIdx.y * 128;
    const int bn0 = blockIdx.x * 128;

    const __half* A = A0 + (size_t)bm0 * K;
    const __half* B = B0 + (size_t)bn0 * K;

    float acc[4][4][4];
#pragma unroll
    for (int a = 0; a < 4; a++)
#pragma unroll
        for (int b = 0; b < 4; b++)
#pragma unroll
            for (int c = 0; c < 4; c++) acc[a][b][c] = 0.f;

    const int arow = (lane & 7) + ((lane >> 3) & 1) * 8;
    const int acol = ((lane >> 4) & 1) * 8;
    const int brow = (lane & 7) + ((lane >> 4) & 1) * 8;
    const int bcol = ((lane >> 3) & 1) * 8;

    const int nch = K / BKC;     // >= 16 for all our shapes

    // prologue: stage chunks 0 and 1
    load_chunk(sb, A, B, K, 0, tid);
    CP_COMMIT();
    load_chunk(sb + BUFB, A, B, K, BKC, tid);
    CP_COMMIT();
    CP_WAIT1();                  // chunk 0 landed (chunk 1 may be in flight)
    __syncthreads();

    int stage = 0;
    for (int i = 0; i < nch; i++) {
        const uint32_t buf = sb + stage * BUFB;
        // compute chunk i
#pragma unroll
        for (int kk = 0; kk < 4; kk++) {
            const int kb = kk * 16;
            uint32_t af[4][4], bf[2][4];
#pragma unroll
            for (int mt = 0; mt < 4; mt++) {
                int r = wm * 64 + mt * 16 + arow;
                ldm_x4(af[mt], buf + (uint32_t)(r * AST + kb + acol) * 2);
            }
#pragma unroll
            for (int nt2 = 0; nt2 < 2; nt2++) {
                int r = wn * 32 + nt2 * 16 + brow;
                ldm_x4(bf[nt2], buf + TILE_B2 + (uint32_t)(r * AST + kb + bcol) * 2);
            }
#pragma unroll
            for (int mt = 0; mt < 4; mt++)
#pragma unroll
                for (int nt = 0; nt < 4; nt++)
                    mma_f16(acc[mt][nt], af[mt], &bf[nt >> 1][(nt & 1) * 2]);
        }
        // stage chunk i+2 into the buffer freed at iteration i-1
        if (i + 2 < nch) {
            int s2 = stage + 2; if (s2 >= 3) s2 -= 3;
            load_chunk(sb + s2 * BUFB, A, B, K, (i + 2) * BKC, tid);
            CP_COMMIT();
            CP_WAIT1();          // chunk i+1 landed
        } else {
            CP_WAIT0();          // drain tail
        }
        __syncthreads();
        if (++stage == 3) stage = 0;
    }

    const int tr = lane >> 2, tc = (lane & 3) * 2;
    const int r0 = bm0 + wm * 64;
    const int c0 = bn0 + wn * 32;
#pragma unroll
    for (int mt = 0; mt < 4; mt++) {
#pragma unroll
        for (int nt = 0; nt < 4; nt++) {
            const int col = c0 + nt * 8 + tc;
            const float2 bv = *(const float2*)(bias + col);
#pragma unroll
            for (int h = 0; h < 2; h++) {
                const int row = r0 + mt * 16 + tr + h * 8;
                float v0 = acc[mt][nt][h * 2 + 0] + bv.x;
                float v1 = acc[mt][nt][h * 2 + 1] + bv.y;
                if (relu) { v0 = fmaxf(v0, 0.f); v1 = fmaxf(v1, 0.f); }
                if (Cf) {
                    float2 o = {v0, v1};
                    *(float2*)(Cf + (size_t)row * N + col) = o;
                } else {
                    *(uint32_t*)(Ch + (size_t)row * N + col) = packh2(v0, v1);
                }
            }
        }
    }
}

// ============================================================
// conversions
// ============================================================
__global__ __launch_bounds__(256) void convert_h(const float* __restrict__ in,
    __half* __restrict__ oh, int n8)
{
    int i = blockIdx.x * 256 + threadIdx.x;
    if (i >= n8) return;
    float4 a = ((const float4*)in)[2 * i];
    float4 b = ((const float4*)in)[2 * i + 1];
    uint4 o;
    o.x = packh2(a.x, a.y); o.y = packh2(a.z, a.w);
    o.z = packh2(b.x, b.y); o.w = packh2(b.z, b.w);
    ((uint4*)oh)[i] = o;
}

// weight [K,N] fp32 -> [N,K] fp16 (transpose)
__global__ void convert_wT(const float* __restrict__ in,
    __half* __restrict__ ohi, int K, int N)
{
    __shared__ float t[32][33];
    int n0 = blockIdx.x * 32, k0 = blockIdx.y * 32;
    int tx = threadIdx.x, ty = threadIdx.y;
    for (int j = ty; j < 32; j += 8) t[j][tx] = in[(size_t)(k0 + j) * N + n0 + tx];
    __syncthreads();
    for (int j = ty; j < 32; j += 8)
        ohi[(size_t)(n0 + j) * K + k0 + tx] = __float2half_rn(t[tx][j]);
}

// ============================================================
// fp16 tensor-core flash attention. CTA: 128 queries of one (b,h).
// 4 warps x 32 rows; KV tiles of 64, cp.async double-buffered.
// Q pre-scaled by log2(e)/8 -> logits in log2 domain; P = ex2.f16x2.
// Row-sum l computed by the tensor core via a ones-column fragment.
// smem: Q 16KB | K0 8KB | V0 8KB | K1 8KB | V1 8KB = 48KB dynamic.
// ============================================================
#define ASM_Q   0
#define ASM_KV  16384
#define ASM_KVB 16384            // per-stage K+V bytes
#define ASM_TOTAL 49152

__device__ __forceinline__ uint32_t asw(int row, int c8) {   // elem offset, 64-elem rows
    return (uint32_t)(row * 64 + (((c8) ^ (row & 7)) << 3));
}

__device__ __forceinline__ void attn_load_kv(uint32_t kvb, const __half* base,
                                             int kt, int tid)
{
#pragma unroll
    for (int j = 0; j < 4; j++) {
        int v = tid + 128 * j;
        int row = v >> 3, c8 = v & 7;
        const __half* src = base + (size_t)(kt * 64 + row) * (3 * CD) + c8 * 8;
        uint32_t dst = kvb + asw(row, c8) * 2;
        CP_ASYNC16(dst, src + CD);              // K
        CP_ASYNC16(dst + 8192, src + 2 * CD);   // V
    }
}

__global__ __launch_bounds__(128) void attn_mma(const __half* __restrict__ qkv,
    __half* __restrict__ ctx)
{
    extern __shared__ char asm_smem[];
    const uint32_t sbase = smem_to_u32(asm_smem);
    const uint32_t qsb = sbase + ASM_Q;

    const int tid = threadIdx.x, lane = tid & 31, w = tid >> 5;
    const int b = blockIdx.y >> 4, h = blockIdx.y & 15;
    const int t0 = blockIdx.x * 128;
    const __half* base = qkv + (size_t)b * TT * (3 * CD) + h * DKD;

    // prefetch KV tile 0 while we set up Q
    attn_load_kv(sbase + ASM_KV, base, 0, tid);
    CP_COMMIT();

    // load Q row `tid`, prescale by log2(e)/8 in fp32, swizzle into smem
    {
        const __half* src = base + (size_t)(t0 + tid) * (3 * CD);
        const float qs = 0.1803368801f;   // log2(e) / 8
#pragma unroll
        for (int c8 = 0; c8 < 8; c8++) {
            uint4 d = *(const uint4*)(src + c8 * 8);
            __half2* p = (__half2*)&d;
#pragma unroll
            for (int u = 0; u < 4; u++) {
                float2 f = __half22float2(p[u]);
                p[u] = __floats2half2_rn(f.x * qs, f.y * qs);
            }
            *(uint4*)&((__half*)asm_smem)[asw(tid, c8)] = d;
        }
    }
    __syncthreads();

    const int arow = (lane & 15);
    const int ac8  = (lane >> 4);
    const int brow = (lane & 7) + ((lane >> 4) & 1) * 8;
    const int bc8  = ((lane >> 3) & 1);
    const int trow = (lane & 7) + ((lane >> 3) & 1) * 8;
    const int tc8  = ((lane >> 4) & 1);
    const int tr = lane >> 2, tc = (lane & 3) * 2;

    // ones-column B fragment (V_extra[k][0]=1): lanes 0-3 hold col 0
    uint32_t onesb[2];
    onesb[0] = onesb[1] = (lane < 4) ? 0x3C003C00u : 0u;

    // hoist Q fragments (loop-invariant): 2 mt x 4 kb x 4 regs
    uint32_t qfr[2][4][4];
#pragma unroll
    for (int mt = 0; mt < 2; mt++)
#pragma unroll
        for (int kb = 0; kb < 4; kb++)
            ldm_x4(qfr[mt][kb], qsb + asw(w * 32 + mt * 16 + arow, kb * 2 + ac8) * 2);

    float O[2][8][4];
#pragma unroll
    for (int mt = 0; mt < 2; mt++)
#pragma unroll
        for (int nt = 0; nt < 8; nt++)
#pragma unroll
            for (int c = 0; c < 4; c++) O[mt][nt][c] = 0.f;
    float Oe[2][4];                      // ones-column accumulator (l in col 0)
#pragma unroll
    for (int mt = 0; mt < 2; mt++)
#pragma unroll
        for (int c = 0; c < 4; c++) Oe[mt][c] = 0.f;
    float mrow[2][2];
#pragma unroll
    for (int mt = 0; mt < 2; mt++) { mrow[mt][0] = mrow[mt][1] = -INFINITY; }

    const int NKT = TT / 64;
    for (int kt = 0; kt < NKT; kt++) {
        if (kt + 1 < NKT) {
            attn_load_kv(sbase + ASM_KV + ((kt + 1) & 1) * ASM_KVB, base, kt + 1, tid);
            CP_COMMIT();
            CP_WAIT1();
        } else {
            CP_WAIT0();
        }
        __syncthreads();

        const uint32_t ksb = sbase + ASM_KV + (kt & 1) * ASM_KVB;
        const uint32_t vsb = ksb + 8192;

        // S = Q @ K^T   (S already in log2 domain)
        float S[2][8][4];
#pragma unroll
        for (int mt = 0; mt < 2; mt++)
#pragma unroll
            for (int nt = 0; nt < 8; nt++)
#pragma unroll
                for (int c = 0; c < 4; c++) S[mt][nt][c] = 0.f;

#pragma unroll
        for (int kb = 0; kb < 4; kb++) {
            uint32_t kf[4][4];
#pragma unroll
            for (int p = 0; p < 4; p++)
                ldm_x4(kf[p], ksb + asw(p * 16 + brow, kb * 2 + bc8) * 2);
#pragma unroll
            for (int mt = 0; mt < 2; mt++)
#pragma unroll
                for (int nt = 0; nt < 8; nt++)
                    mma_f16(S[mt][nt], qfr[mt][kb], &kf[nt >> 1][(nt & 1) * 2]);
        }

        // online softmax: P = 2^(S - m), packed fp16 via ex2.approx.f16x2
        uint32_t pf[2][4][4];
#pragma unroll
        for (int mt = 0; mt < 2; mt++) {
            float mx0 = -INFINITY, mx1 = -INFINITY;
#pragma unroll
            for (int nt = 0; nt < 8; nt++) {
                mx0 = fmaxf(mx0, fmaxf(S[mt][nt][0], S[mt][nt][1]));
                mx1 = fmaxf(mx1, fmaxf(S[mt][nt][2], S[mt][nt][3]));
            }
            mx0 = fmaxf(mx0, __shfl_xor_sync(0xffffffffu, mx0, 1, 4));
            mx0 = fmaxf(mx0, __shfl_xor_sync(0xffffffffu, mx0, 2, 4));
            mx1 = fmaxf(mx1, __shfl_xor_sync(0xffffffffu, mx1, 1, 4));
            mx1 = fmaxf(mx1, __shfl_xor_sync(0xffffffffu, mx1, 2, 4));
            float mn0 = fmaxf(mrow[mt][0], mx0);
            float mn1 = fmaxf(mrow[mt][1], mx1);
            float a0 = exp2f(mrow[mt][0] - mn0);
            float a1 = exp2f(mrow[mt][1] - mn1);
            mrow[mt][0] = mn0; mrow[mt][1] = mn1;
#pragma unroll
            for (int g = 0; g < 4; g++) {
                pf[mt][g][0] = ex2h2(S[mt][2 * g][0] - mn0, S[mt][2 * g][1] - mn0);
                pf[mt][g][1] = ex2h2(S[mt][2 * g][2] - mn1, S[mt][2 * g][3] - mn1);
                pf[mt][g][2] = ex2h2(S[mt][2 * g + 1][0] - mn0, S[mt][2 * g + 1][1] - mn0);
                pf[mt][g][3] = ex2h2(S[mt][2 * g + 1][2] - mn1, S[mt][2 * g + 1][3] - mn1);
            }
#pragma unroll
            for (int nt = 0; nt < 8; nt++) {
                O[mt][nt][0] *= a0; O[mt][nt][1] *= a0;
                O[mt][nt][2] *= a1; O[mt][nt][3] *= a1;
            }
            Oe[mt][0] *= a0; Oe[mt][1] *= a0;
            Oe[mt][2] *= a1; Oe[mt][3] *= a1;
        }

        // O += P @ V ; Oe += P @ ones (row sum -> l)
#pragma unroll
        for (int kb = 0; kb < 4; kb++) {
            uint32_t vf[4][4];
#pragma unroll
            for (int p = 0; p < 4; p++)
                ldm_x4t(vf[p], vsb + asw(kb * 16 + trow, p * 2 + tc8) * 2);
#pragma unroll
            for (int mt = 0; mt < 2; mt++) {
#pragma unroll
                for (int nt = 0; nt < 8; nt++)
                    mma_f16(O[mt][nt], pf[mt][kb], &vf[nt >> 1][(nt & 1) * 2]);
                mma_f16(Oe[mt], pf[mt][kb], onesb);
            }
        }
        __syncthreads();
    }

    // epilogue: broadcast l from ones column, normalize, store ctx fp16
#pragma unroll
    for (int mt = 0; mt < 2; mt++) {
        float l0 = __shfl_sync(0xffffffffu, Oe[mt][0], lane & ~3);
        float l1 = __shfl_sync(0xffffffffu, Oe[mt][2], lane & ~3);
        float inv0 = 1.f / l0;
        float inv1 = 1.f / l1;
#pragma unroll
        for (int nt = 0; nt < 8; nt++) {
#pragma unroll
            for (int hr = 0; hr < 2; hr++) {
                float inv = hr ? inv1 : inv0;
                float v0 = O[mt][nt][hr * 2 + 0] * inv;
                float v1 = O[mt][nt][hr * 2 + 1] * inv;
                int row = t0 + w * 32 + mt * 16 + tr + hr * 8;
                size_t off = (size_t)(b * TT + row) * CD + h * DKD + nt * 8 + tc;
                *(uint32_t*)(ctx + off) = packh2(v0, v1);
            }
        }
    }
}

// ============================================================
// out = LayerNorm(x + res); optional fp16 emission
// ============================================================
__global__ __launch_bounds__(256) void add_ln_kernel(
    const float* __restrict__ x, const float* __restrict__ res,
    const float* __restrict__ gg, const float* __restrict__ bb,
    float* __restrict__ out, __half* __restrict__ oh)
{
    const int row = blockIdx.x, tid = threadIdx.x;
    float4 xv = ((const float4*)(x + (size_t)row * CD))[tid];
    float4 rv = ((const float4*)(res + (size_t)row * CD))[tid];
    float y0 = xv.x + rv.x, y1 = xv.y + rv.y, y2 = xv.z + rv.z, y3 = xv.w + rv.w;
    float s = y0 + y1 + y2 + y3;
    float ss = y0 * y0 + y1 * y1 + y2 * y2 + y3 * y3;
#pragma unroll
    for (int off = 16; off; off >>= 1) {
        s  += __shfl_xor_sync(0xffffffffu, s, off);
        ss += __shfl_xor_sync(0xffffffffu, ss, off);
    }
    __shared__ float rs[8], rss[8];
    if ((tid & 31) == 0) { rs[tid >> 5] = s; rss[tid >> 5] = ss; }
    __syncthreads();
    float tot = 0.f, tots = 0.f;
#pragma unroll
    for (int i = 0; i < 8; i++) { tot += rs[i]; tots += rss[i]; }
    float mean = tot * (1.f / CD);
    float var = tots * (1.f / CD) - mean * mean;
    float iv = rsqrtf(var + 1e-5f);
    float4 gv = ((const float4*)gg)[tid];
    float4 bv = ((const float4*)bb)[tid];
    float w0 = (y0 - mean) * iv * gv.x + bv.x;
    float w1 = (y1 - mean) * iv * gv.y + bv.y;
    float w2 = (y2 - mean) * iv * gv.z + bv.z;
    float w3 = (y3 - mean) * iv * gv.w + bv.w;
    float4 ov = {w0, w1, w2, w3};
    ((float4*)(out + (size_t)row * CD))[tid] = ov;
    if (oh) {
        uint2 o;
        o.x = packh2(w0, w1);
        o.y = packh2(w2, w3);
        *(uint2*)(oh + (size_t)row * CD + tid * 4) = o;
    }
}

// ============================================================
extern "C" void kernel_launch(void* const* d_in, const int* in_sizes, int n_in,
                              void* d_out, int out_size)
{
    const float* x     = (const float*)d_in[0];
    const float* w_qkv = (const float*)d_in[1];
    const float* b_qkv = (const float*)d_in[2];
    const float* w_out = (const float*)d_in[3];
    const float* b_out = (const float*)d_in[4];
    const float* w1    = (const float*)d_in[5];
    const float* b1    = (const float*)d_in[6];
    const float* w2    = (const float*)d_in[7];
    const float* b2    = (const float*)d_in[8];
    const float* ln1g  = (const float*)d_in[9];
    const float* ln1b  = (const float*)d_in[10];
    const float* ln2g  = (const float*)d_in[11];
    const float* ln2b  = (const float*)d_in[12];
    float* out = (float*)d_out;

    float *tmp, *x1;
    __half *qkvh, *ah, *ctxh, *hh, *wth;
    cudaGetSymbolAddress((void**)&qkvh, g_qkvh);
    cudaGetSymbolAddress((void**)&tmp,  g_tmp);
    cudaGetSymbolAddress((void**)&x1,   g_x1);
    cudaGetSymbolAddress((void**)&ah,   g_ah);
    cudaGetSymbolAddress((void**)&ctxh, g_ctxh);
    cudaGetSymbolAddress((void**)&hh,   g_hh);
    cudaGetSymbolAddress((void**)&wth,  g_wth);

    cudaFuncSetAttribute(gemm_mma, cudaFuncAttributeMaxDynamicSharedMemorySize, GSM_BYTES);
    cudaFuncSetAttribute(attn_mma, cudaFuncAttributeMaxDynamicSharedMemorySize, ASM_TOTAL);

    dim3 tblk(32, 8);

    // x -> fp16
    convert_h<<<(BT * CD / 8 + 255) / 256, 256>>>(x, ah, BT * CD / 8);
    // qkv = x @ w_qkv + b_qkv  (out fp16)
    convert_wT<<<dim3(3 * CD / 32, CD / 32), tblk>>>(w_qkv, wth, CD, 3 * CD);
    gemm_mma<<<dim3(3 * CD / 128, BT / 128), 256, GSM_BYTES>>>(
        ah, wth, b_qkv, nullptr, qkvh, 3 * CD, CD, 0);
    // ctx = attention(qkv) -> fp16
    attn_mma<<<dim3(TT / 128, NB * NH), 128, ASM_TOTAL>>>(qkvh, ctxh);
    // attn_out = ctx @ w_out + b_out (out fp32)
    convert_wT<<<dim3(CD / 32, CD / 32), tblk>>>(w_out, wth, CD, CD);
    gemm_mma<<<dim3(CD / 128, BT / 128), 256, GSM_BYTES>>>(
        ctxh, wth, b_out, tmp, nullptr, CD, CD, 0);
    // x1 = LN(x + attn_out), emit fp16 into ah
    add_ln_kernel<<<BT, 256>>>(x, tmp, ln1g, ln1b, x1, ah);
    // h = relu(x1 @ w1 + b1) (out fp16)
    convert_wT<<<dim3(FFD / 32, CD / 32), tblk>>>(w1, wth, CD, FFD);
    gemm_mma<<<dim3(FFD / 128, BT / 128), 256, GSM_BYTES>>>(
        ah, wth, b1, nullptr, hh, FFD, CD, 1);
    // ffn_out = h @ w2 + b2 (out fp32)
    convert_wT<<<dim3(CD / 32, FFD / 32), tblk>>>(w2, wth, FFD, CD);
    gemm_mma<<<dim3(CD / 128, BT / 128), 256, GSM_BYTES>>>(
        hh, wth, b2, tmp, nullptr, CD, FFD, 0);
    // out = LN(x1 + ffn_out)
    add_ln_kernel<<<BT, 256>>>(x1, tmp, ln2g, ln2b, out, nullptr);
}